// round 9
// baseline (speedup 1.0000x reference)
#include <cuda_runtime.h>
#include <math.h>

#define Bn 32
#define Nn 1000
#define Cn 105
#define NC 104            // classes 1..104
#define SCORE_TH 0.05f
#define NMS_TH 0.5f
#define DETS 100
#define IMG_W 1333.0f
#define IMG_H 800.0f
#define BBOX_CLIP 4.135166556742356f   // log(1000/16)
#define MAXCAND 1024                   // per (image,class) candidate cap; K <= 1000
#define GCAP 512                       // gather capacity for final small sort (pow2)
#define ROWS_PER_CTA 8                 // warps per CTA in softmax kernel
#define SCACHE 6144                    // shared score-bit cache in topk
#define AMB_BAND 1e-5f                 // threshold ambiguity band for fast-exp guard

// ---------------- scratch (device globals; no allocation allowed) ----------------
__device__ float  d_cand_score[Bn][NC][Nn];
__device__ float4 d_cand_box[Bn][NC][Nn];
__device__ int    d_cand_n[Bn][NC][Nn];
__device__ int    d_cand_cnt[Bn * NC];

__device__ float  d_det_score[Bn][NC * Nn];
__device__ float4 d_det_box[Bn][NC * Nn];
__device__ int    d_det_label[Bn][NC * Nn];
__device__ int    d_img_cnt[Bn];

// ---------------- kernel 0: zero counters (graph-replay safe) ----------------
__global__ void zero_counters_kernel() {
    int i = blockIdx.x * blockDim.x + threadIdx.x;
    if (i < Bn * NC) d_cand_cnt[i] = 0;
    if (i < Bn) d_img_cnt[i] = 0;
}

// ---------------- kernel 1: warp-per-row softmax + threshold + decode ----------------
// Fast __expf for denominator + threshold decision (with exact-recheck band);
// precise expf numerator for stored scores and box decode.
__global__ void softmax_gather_kernel(const float* __restrict__ logits,
                                      const float* __restrict__ boxreg,
                                      const float* __restrict__ props) {
    const int wid = threadIdx.x >> 5;
    const int lane = threadIdx.x & 31;
    const int row = blockIdx.x * ROWS_PER_CTA + wid;   // grid = B*N/8 = 4000
    const int b = row / Nn;
    const int n = row % Nn;

    const float* L = logits + (size_t)row * Cn;

    float l[4];
    #pragma unroll
    for (int q = 0; q < 4; q++) {
        const int j = lane + 32 * q;
        l[q] = (j < Cn) ? L[j] : -INFINITY;
    }

    // warp max
    float mx = fmaxf(fmaxf(l[0], l[1]), fmaxf(l[2], l[3]));
    #pragma unroll
    for (int o = 16; o > 0; o >>= 1) mx = fmaxf(mx, __shfl_xor_sync(0xffffffffu, mx, o));

    // fast exp sum
    float eh[4];
    float s = 0.0f;
    #pragma unroll
    for (int q = 0; q < 4; q++) {
        const int j = lane + 32 * q;
        eh[q] = (j < Cn) ? __expf(l[q] - mx) : 0.0f;
        s += eh[q];
    }
    #pragma unroll
    for (int o = 16; o > 0; o >>= 1) s += __shfl_xor_sync(0xffffffffu, s, o);
    float inv_s = 1.0f / s;

    // approx probabilities + ambiguity detection near threshold
    float ph[4];
    bool amb = false;
    #pragma unroll
    for (int q = 0; q < 4; q++) {
        const int j = lane + 32 * q;
        ph[q] = eh[q] * inv_s;
        if (j >= 1 && j < Cn && fabsf(ph[q] - SCORE_TH) < AMB_BAND) amb = true;
    }
    bool precise_row = false;
    if (__ballot_sync(0xffffffffu, amb)) {
        // rare: redo entire row precisely
        float sp = 0.0f;
        #pragma unroll
        for (int q = 0; q < 4; q++) {
            const int j = lane + 32 * q;
            eh[q] = (j < Cn) ? expf(l[q] - mx) : 0.0f;
            sp += eh[q];
        }
        #pragma unroll
        for (int o = 16; o > 0; o >>= 1) sp += __shfl_xor_sync(0xffffffffu, sp, o);
        inv_s = 1.0f / sp;
        #pragma unroll
        for (int q = 0; q < 4; q++) ph[q] = eh[q] * inv_s;
        precise_row = true;
    }

    // proposal geometry (same address across warp -> broadcast load)
    const float4 pr = *(const float4*)(props + (size_t)row * 4);
    const float w  = pr.z - pr.x + 1.0f;
    const float h  = pr.w - pr.y + 1.0f;
    const float cx = pr.x + 0.5f * w;
    const float cy = pr.y + 0.5f * h;

    #pragma unroll
    for (int q = 0; q < 4; q++) {
        const int j = lane + 32 * q;
        if (j >= 1 && j < Cn && ph[q] > SCORE_TH) {
            // stored score: precise numerator over (approx or precise) sum
            const float p_store = precise_row ? ph[q] : expf(l[q] - mx) * inv_s;

            const float4 r = *(const float4*)(boxreg + ((size_t)row * Cn + j) * 4);
            const float dx = r.x / 10.0f;
            const float dy = r.y / 10.0f;
            const float dw = fminf(r.z / 5.0f, BBOX_CLIP);
            const float dh = fminf(r.w / 5.0f, BBOX_CLIP);
            const float pcx = dx * w + cx;
            const float pcy = dy * h + cy;
            const float pw = expf(dw) * w;
            const float ph2 = expf(dh) * h;
            float4 box;
            box.x = fminf(fmaxf(pcx - 0.5f * pw, 0.0f), IMG_W - 1.0f);
            box.y = fminf(fmaxf(pcy - 0.5f * ph2, 0.0f), IMG_H - 1.0f);
            box.z = fminf(fmaxf(pcx + 0.5f * pw - 1.0f, 0.0f), IMG_W - 1.0f);
            box.w = fminf(fmaxf(pcy + 0.5f * ph2 - 1.0f, 0.0f), IMG_H - 1.0f);

            const int c = j - 1;
            const int slot = atomicAdd(&d_cand_cnt[b * NC + c], 1);
            d_cand_score[b][c][slot] = p_store;
            d_cand_n[b][c][slot] = n;
            d_cand_box[b][c][slot] = box;
        }
    }
}

// ---------------- kernel 2a: warp-level NMS for K <= 32 ----------------
__global__ void nms_warp_kernel() {
    const int wid = threadIdx.x >> 5;
    const int lane = threadIdx.x & 31;
    const int cell = blockIdx.x * 8 + wid;
    if (cell >= Bn * NC) return;
    const int K = d_cand_cnt[cell];
    if (K == 0 || K > 32) return;
    const int b = cell / NC;
    const int c = cell % NC;

    if (K == 1) {
        if (lane == 0) {
            const int pos = atomicAdd(&d_img_cnt[b], 1);
            d_det_score[b][pos] = d_cand_score[b][c][0];
            d_det_box[b][pos] = d_cand_box[b][c][0];
            d_det_label[b][pos] = c + 1;
        }
        return;
    }

    const bool act = lane < K;
    const float sc = act ? d_cand_score[b][c][lane] : -INFINITY;
    const int   nn = act ? d_cand_n[b][c][lane] : 0x7fffffff;
    float4 bx = make_float4(0.0f, 0.0f, 0.0f, 0.0f);
    if (act) bx = d_cand_box[b][c][lane];

    // rank = #elements strictly better (score desc, proposal-index asc; keys unique)
    int rank = 0;
    #pragma unroll 8
    for (int l = 0; l < 32; l++) {
        const float osc = __shfl_sync(0xffffffffu, sc, l);
        const int   onn = __shfl_sync(0xffffffffu, nn, l);
        if (osc > sc || (osc == sc && onn < nn)) rank++;
    }

    const float area = (bx.z - bx.x + 1.0f) * (bx.w - bx.y + 1.0f);
    int supp = 0;
    for (int t = 0; t < K - 1; t++) {
        const unsigned mt = __ballot_sync(0xffffffffu, rank == t);
        const int src = __ffs(mt) - 1;
        const int cs = __shfl_sync(0xffffffffu, supp, src);
        const float ax1 = __shfl_sync(0xffffffffu, bx.x, src);
        const float ay1 = __shfl_sync(0xffffffffu, bx.y, src);
        const float ax2 = __shfl_sync(0xffffffffu, bx.z, src);
        const float ay2 = __shfl_sync(0xffffffffu, bx.w, src);
        const float aarea = __shfl_sync(0xffffffffu, area, src);
        if (!cs && act && !supp && rank > t) {
            const float iw = fmaxf(fminf(ax2, bx.z) - fmaxf(ax1, bx.x) + 1.0f, 0.0f);
            const float ih = fmaxf(fminf(ay2, bx.w) - fmaxf(ay1, bx.y) + 1.0f, 0.0f);
            const float inter = iw * ih;
            const float iou = inter / (aarea + area - inter);
            if (iou > NMS_TH) supp = 1;
        }
    }

    const bool keep = act && !supp;
    const unsigned km = __ballot_sync(0xffffffffu, keep);
    const int cnt = __popc(km);
    if (cnt == 0) return;
    const int leader = __ffs(km) - 1;
    int base = 0;
    if (lane == leader) base = atomicAdd(&d_img_cnt[b], cnt);
    base = __shfl_sync(0xffffffffu, base, leader);
    if (keep) {
        const int pos = base + __popc(km & ((1u << lane) - 1u));
        d_det_score[b][pos] = sc;
        d_det_box[b][pos] = bx;
        d_det_label[b][pos] = c + 1;
    }
}

// ---------------- kernel 2b: block NMS for K > 32 ----------------
__global__ void nms_block_kernel() {
    const int bc = blockIdx.x;           // 0 .. B*NC-1
    const int K = d_cand_cnt[bc];
    if (K <= 32) return;                 // handled by warp kernel
    const int b = bc / NC;
    const int c = bc % NC;
    const int tid = threadIdx.x;         // 256 threads

    __shared__ float  ss[MAXCAND];
    __shared__ int    sn[MAXCAND];
    __shared__ short  sslot[MAXCAND];
    __shared__ float4 sbox[MAXCAND];
    __shared__ unsigned char supp[MAXCAND];

    int P = 1;
    while (P < K) P <<= 1;   // P <= 1024

    for (int i = tid; i < P; i += 256) {
        if (i < K) {
            ss[i] = d_cand_score[b][c][i];
            sn[i] = d_cand_n[b][c][i];
            sbox[i] = d_cand_box[b][c][i];
            supp[i] = 0;
        } else {
            ss[i] = -INFINITY;
            sn[i] = 0x7fffffff;
            supp[i] = 1;
        }
        sslot[i] = (short)i;
    }
    __syncthreads();

    // bitonic sort: score desc, proposal-index asc
    for (int k = 2; k <= P; k <<= 1) {
        for (int j = k >> 1; j > 0; j >>= 1) {
            for (int i = tid; i < P; i += 256) {
                const int ixj = i ^ j;
                if (ixj > i) {
                    const float a = ss[i], bb = ss[ixj];
                    const int   na = sn[i], nb = sn[ixj];
                    const bool i_after = (a < bb) || (a == bb && na > nb);
                    const bool dirAsc = ((i & k) == 0);
                    if (i_after == dirAsc) {
                        ss[i] = bb;  ss[ixj] = a;
                        sn[i] = nb;  sn[ixj] = na;
                        const short t = sslot[i]; sslot[i] = sslot[ixj]; sslot[ixj] = t;
                    }
                }
            }
            __syncthreads();
        }
    }

    // greedy NMS (reference-exact IoU compare)
    for (int i = 0; i < K; i++) {
        __syncthreads();
        if (supp[i]) continue;
        const float4 A = sbox[sslot[i]];
        const float areaA = (A.z - A.x + 1.0f) * (A.w - A.y + 1.0f);
        for (int j = i + 1 + tid; j < K; j += 256) {
            if (supp[j]) continue;
            const float4 Bx = sbox[sslot[j]];
            const float iw = fmaxf(fminf(A.z, Bx.z) - fmaxf(A.x, Bx.x) + 1.0f, 0.0f);
            const float ih = fmaxf(fminf(A.w, Bx.w) - fmaxf(A.y, Bx.y) + 1.0f, 0.0f);
            const float inter = iw * ih;
            const float areaB = (Bx.z - Bx.x + 1.0f) * (Bx.w - Bx.y + 1.0f);
            const float iou = inter / (areaA + areaB - inter);
            if (iou > NMS_TH) supp[j] = 1;
        }
    }
    __syncthreads();

    for (int i = tid; i < K; i += 256) {
        if (!supp[i]) {
            const int pos = atomicAdd(&d_img_cnt[b], 1);
            d_det_score[b][pos] = ss[i];
            d_det_box[b][pos] = sbox[sslot[i]];
            d_det_label[b][pos] = c + 1;
        }
    }
}

// ---------------- kernel 3: per-image top-100 via radix select + tiny sort ----------------
// Output layout (float32): det [B,100,5] | labels [B,100] | valid [B,100]
__global__ void topk_kernel(float* __restrict__ out) {
    const int b = blockIdx.x;
    const int tid = threadIdx.x;     // 1024
    const int M = d_img_cnt[b];

    float* detOut = out + (size_t)b * DETS * 5;
    float* labOut = out + (size_t)Bn * DETS * 5 + (size_t)b * DETS;
    float* valOut = out + (size_t)Bn * DETS * 5 + (size_t)Bn * DETS + (size_t)b * DETS;

    __shared__ int hist[256];
    __shared__ unsigned s_prefix;
    __shared__ int s_rank;
    __shared__ int s_cnt;
    __shared__ unsigned long long keys[GCAP];
    __shared__ unsigned sbits[SCACHE];

    const bool cached = (M <= SCACHE);
    if (cached) {
        for (int i = tid; i < M; i += 1024)
            sbits[i] = __float_as_uint(d_det_score[b][i]);
        __syncthreads();
    }

    // -------- phase 1: radix select the bit-pattern T of the DETS-th largest score --------
    unsigned T = 0u;                 // if M < DETS: keep everything
    if (M >= DETS) {
        if (tid == 0) { s_prefix = 0u; s_rank = DETS; }
        __syncthreads();
        for (int shift = 24; shift >= 0; shift -= 8) {
            for (int i = tid; i < 256; i += 1024) hist[i] = 0;
            __syncthreads();
            const unsigned pfx = s_prefix;
            const unsigned hmask = (shift == 24) ? 0u : (0xffffffffu << (shift + 8));
            for (int i = tid; i < M; i += 1024) {
                const unsigned bits = cached ? sbits[i]
                                             : __float_as_uint(d_det_score[b][i]);
                if ((bits & hmask) == (pfx & hmask))
                    atomicAdd(&hist[(bits >> shift) & 255], 1);
            }
            __syncthreads();
            if (tid == 0) {
                int cum = 0, rank = s_rank, dsel = 0;
                for (int d = 255; d >= 0; d--) {
                    if (cum + hist[d] >= rank) { dsel = d; s_rank = rank - cum; break; }
                    cum += hist[d];
                }
                s_prefix |= (unsigned)dsel << shift;
            }
            __syncthreads();
        }
        T = s_prefix;
    }

    // -------- phase 2: gather all elements with bits >= T --------
    if (tid == 0) s_cnt = 0;
    __syncthreads();
    for (int i = tid; i < M; i += 1024) {
        const unsigned bits = cached ? sbits[i] : __float_as_uint(d_det_score[b][i]);
        if (bits >= T) {
            const int p = atomicAdd(&s_cnt, 1);
            if (p < GCAP)
                keys[p] = ((unsigned long long)bits << 32) |
                          (unsigned)(0x7fffffff - i);
        }
    }
    __syncthreads();
    const int cnt = (s_cnt < GCAP) ? s_cnt : GCAP;

    int P = 128;                      // P >= DETS, pow2
    while (P < cnt) P <<= 1;          // P <= GCAP
    for (int i = cnt + tid; i < P; i += 1024) keys[i] = 0ull;
    __syncthreads();

    // -------- phase 3: bitonic sort (descending) of <= GCAP keys --------
    for (int k = 2; k <= P; k <<= 1) {
        for (int j = k >> 1; j > 0; j >>= 1) {
            for (int i = tid; i < P; i += 1024) {
                const int ixj = i ^ j;
                if (ixj > i) {
                    const unsigned long long a = keys[i], c = keys[ixj];
                    const bool descBlock = ((i & k) == 0);
                    if (descBlock ? (a < c) : (a > c)) {
                        keys[i] = c; keys[ixj] = a;
                    }
                }
            }
            __syncthreads();
        }
    }

    // -------- phase 4: parallel output write --------
    if (tid < DETS) {
        const unsigned long long key = keys[tid];
        if (tid < cnt && key != 0ull) {
            const int idx = 0x7fffffff - (int)(unsigned)(key & 0xffffffffull);
            const float score = __uint_as_float((unsigned)(key >> 32));
            const float4 bx = d_det_box[b][idx];
            detOut[tid * 5 + 0] = bx.x;
            detOut[tid * 5 + 1] = bx.y;
            detOut[tid * 5 + 2] = bx.z;
            detOut[tid * 5 + 3] = bx.w;
            detOut[tid * 5 + 4] = score;
            labOut[tid] = (float)d_det_label[b][idx];
            valOut[tid] = 1.0f;
        } else {
            detOut[tid * 5 + 0] = 0.0f;
            detOut[tid * 5 + 1] = 0.0f;
            detOut[tid * 5 + 2] = 0.0f;
            detOut[tid * 5 + 3] = 0.0f;
            detOut[tid * 5 + 4] = 0.0f;
            labOut[tid] = 0.0f;
            valOut[tid] = 0.0f;
        }
    }
}

// ---------------- launch ----------------
extern "C" void kernel_launch(void* const* d_in, const int* in_sizes, int n_in,
                              void* d_out, int out_size) {
    const float* logits = nullptr;
    const float* boxreg = nullptr;
    const float* props  = nullptr;
    for (int i = 0; i < n_in; i++) {
        if (in_sizes[i] == Bn * Nn * Cn)          logits = (const float*)d_in[i];
        else if (in_sizes[i] == Bn * Nn * 4 * Cn) boxreg = (const float*)d_in[i];
        else if (in_sizes[i] == Bn * Nn * 4)      props = (const float*)d_in[i];
    }
    float* out = (float*)d_out;

    zero_counters_kernel<<<(Bn * NC + 255) / 256, 256>>>();
    softmax_gather_kernel<<<(Bn * Nn) / ROWS_PER_CTA, 32 * ROWS_PER_CTA>>>(logits, boxreg, props);
    nms_warp_kernel<<<(Bn * NC + 7) / 8, 256>>>();
    nms_block_kernel<<<Bn * NC, 256>>>();
    topk_kernel<<<Bn, 1024>>>(out);
}

// round 11
// speedup vs baseline: 1.1272x; 1.1272x over previous
#include <cuda_runtime.h>
#include <math.h>

#define Bn 32
#define Nn 1000
#define Cn 105
#define NC 104            // classes 1..104
#define SCORE_TH 0.05f
#define NMS_TH 0.5f
#define DETS 100
#define IMG_W 1333.0f
#define IMG_H 800.0f
#define BBOX_CLIP 4.135166556742356f   // log(1000/16)
#define MAXCAND 1024                   // per (image,class) candidate cap; K <= 1000
#define GCAP 512                       // gather capacity for final small sort (pow2)
#define ROWS_PER_CTA 8                 // warps per CTA in softmax kernel
#define SCACHE 6144                    // shared score-bit cache in topk
#define AMB_BAND 1e-5f                 // threshold ambiguity band for fast-exp guard
#define NMSB_THREADS 128               // block NMS thread count
#define KMASK 320                      // bitmask NMS path limit
#define NWM 10                         // mask words per row (KMASK/32)

// ---------------- scratch (device globals; no allocation allowed) ----------------
__device__ float  d_cand_score[Bn][NC][Nn];
__device__ float4 d_cand_box[Bn][NC][Nn];
__device__ int    d_cand_n[Bn][NC][Nn];
__device__ int    d_cand_cnt[Bn * NC];

__device__ float  d_det_score[Bn][NC * Nn];
__device__ float4 d_det_box[Bn][NC * Nn];
__device__ int    d_det_label[Bn][NC * Nn];
__device__ int    d_img_cnt[Bn];

// ---------------- kernel 0: zero counters (graph-replay safe) ----------------
__global__ void zero_counters_kernel() {
    int i = blockIdx.x * blockDim.x + threadIdx.x;
    if (i < Bn * NC) d_cand_cnt[i] = 0;
    if (i < Bn) d_img_cnt[i] = 0;
}

// ---------------- kernel 1: warp-per-row softmax + threshold + decode ----------------
__global__ void softmax_gather_kernel(const float* __restrict__ logits,
                                      const float* __restrict__ boxreg,
                                      const float* __restrict__ props) {
    const int wid = threadIdx.x >> 5;
    const int lane = threadIdx.x & 31;
    const int row = blockIdx.x * ROWS_PER_CTA + wid;   // grid = B*N/8 = 4000
    const int b = row / Nn;
    const int n = row % Nn;

    const float* L = logits + (size_t)row * Cn;

    float l[4];
    #pragma unroll
    for (int q = 0; q < 4; q++) {
        const int j = lane + 32 * q;
        l[q] = (j < Cn) ? L[j] : -INFINITY;
    }

    float mx = fmaxf(fmaxf(l[0], l[1]), fmaxf(l[2], l[3]));
    #pragma unroll
    for (int o = 16; o > 0; o >>= 1) mx = fmaxf(mx, __shfl_xor_sync(0xffffffffu, mx, o));

    float eh[4];
    float s = 0.0f;
    #pragma unroll
    for (int q = 0; q < 4; q++) {
        const int j = lane + 32 * q;
        eh[q] = (j < Cn) ? __expf(l[q] - mx) : 0.0f;
        s += eh[q];
    }
    #pragma unroll
    for (int o = 16; o > 0; o >>= 1) s += __shfl_xor_sync(0xffffffffu, s, o);
    float inv_s = 1.0f / s;

    float ph[4];
    bool amb = false;
    #pragma unroll
    for (int q = 0; q < 4; q++) {
        const int j = lane + 32 * q;
        ph[q] = eh[q] * inv_s;
        if (j >= 1 && j < Cn && fabsf(ph[q] - SCORE_TH) < AMB_BAND) amb = true;
    }
    bool precise_row = false;
    if (__ballot_sync(0xffffffffu, amb)) {
        float sp = 0.0f;
        #pragma unroll
        for (int q = 0; q < 4; q++) {
            const int j = lane + 32 * q;
            eh[q] = (j < Cn) ? expf(l[q] - mx) : 0.0f;
            sp += eh[q];
        }
        #pragma unroll
        for (int o = 16; o > 0; o >>= 1) sp += __shfl_xor_sync(0xffffffffu, sp, o);
        inv_s = 1.0f / sp;
        #pragma unroll
        for (int q = 0; q < 4; q++) ph[q] = eh[q] * inv_s;
        precise_row = true;
    }

    const float4 pr = *(const float4*)(props + (size_t)row * 4);
    const float w  = pr.z - pr.x + 1.0f;
    const float h  = pr.w - pr.y + 1.0f;
    const float cx = pr.x + 0.5f * w;
    const float cy = pr.y + 0.5f * h;

    #pragma unroll
    for (int q = 0; q < 4; q++) {
        const int j = lane + 32 * q;
        if (j >= 1 && j < Cn && ph[q] > SCORE_TH) {
            const float p_store = precise_row ? ph[q] : expf(l[q] - mx) * inv_s;

            const float4 r = *(const float4*)(boxreg + ((size_t)row * Cn + j) * 4);
            const float dx = r.x / 10.0f;
            const float dy = r.y / 10.0f;
            const float dw = fminf(r.z / 5.0f, BBOX_CLIP);
            const float dh = fminf(r.w / 5.0f, BBOX_CLIP);
            const float pcx = dx * w + cx;
            const float pcy = dy * h + cy;
            const float pw = expf(dw) * w;
            const float ph2 = expf(dh) * h;
            float4 box;
            box.x = fminf(fmaxf(pcx - 0.5f * pw, 0.0f), IMG_W - 1.0f);
            box.y = fminf(fmaxf(pcy - 0.5f * ph2, 0.0f), IMG_H - 1.0f);
            box.z = fminf(fmaxf(pcx + 0.5f * pw - 1.0f, 0.0f), IMG_W - 1.0f);
            box.w = fminf(fmaxf(pcy + 0.5f * ph2 - 1.0f, 0.0f), IMG_H - 1.0f);

            const int c = j - 1;
            const int slot = atomicAdd(&d_cand_cnt[b * NC + c], 1);
            d_cand_score[b][c][slot] = p_store;
            d_cand_n[b][c][slot] = n;
            d_cand_box[b][c][slot] = box;
        }
    }
}

// ---------------- kernel 2a: warp-level NMS for K <= 32 ----------------
__global__ void nms_warp_kernel() {
    const int wid = threadIdx.x >> 5;
    const int lane = threadIdx.x & 31;
    const int cell = blockIdx.x * 8 + wid;
    if (cell >= Bn * NC) return;
    const int K = d_cand_cnt[cell];
    if (K == 0 || K > 32) return;
    const int b = cell / NC;
    const int c = cell % NC;

    if (K == 1) {
        if (lane == 0) {
            const int pos = atomicAdd(&d_img_cnt[b], 1);
            d_det_score[b][pos] = d_cand_score[b][c][0];
            d_det_box[b][pos] = d_cand_box[b][c][0];
            d_det_label[b][pos] = c + 1;
        }
        return;
    }

    const bool act = lane < K;
    const float sc = act ? d_cand_score[b][c][lane] : -INFINITY;
    const int   nn = act ? d_cand_n[b][c][lane] : 0x7fffffff;
    float4 bx = make_float4(0.0f, 0.0f, 0.0f, 0.0f);
    if (act) bx = d_cand_box[b][c][lane];

    // rank = #elements strictly better (score desc, proposal-index asc)
    int rank = 0;
    #pragma unroll 8
    for (int l = 0; l < 32; l++) {
        const float osc = __shfl_sync(0xffffffffu, sc, l);
        const int   onn = __shfl_sync(0xffffffffu, nn, l);
        if (osc > sc || (osc == sc && onn < nn)) rank++;
    }

    const float area = (bx.z - bx.x + 1.0f) * (bx.w - bx.y + 1.0f);

    // suppression bitmask over ranks: my row = ranks I would suppress (rank>mine, iou>th)
    unsigned myrow = 0;
    #pragma unroll 8
    for (int l = 0; l < 32; l++) {
        const int   orank = __shfl_sync(0xffffffffu, rank, l);
        const float ox1 = __shfl_sync(0xffffffffu, bx.x, l);
        const float oy1 = __shfl_sync(0xffffffffu, bx.y, l);
        const float ox2 = __shfl_sync(0xffffffffu, bx.z, l);
        const float oy2 = __shfl_sync(0xffffffffu, bx.w, l);
        const float oarea = __shfl_sync(0xffffffffu, area, l);
        const bool oact = (orank < K);
        if (act && oact && orank > rank) {
            const float iw = fmaxf(fminf(ox2, bx.z) - fmaxf(ox1, bx.x) + 1.0f, 0.0f);
            const float ih = fmaxf(fminf(oy2, bx.w) - fmaxf(oy1, bx.y) + 1.0f, 0.0f);
            const float inter = iw * ih;
            const float iou = inter / (area + oarea - inter);
            if (iou > NMS_TH) myrow |= 1u << orank;
        }
    }
    // all lanes build rank->row table via shuffle (lane l has rank 'rank', row 'myrow')
    unsigned rows[32];
    #pragma unroll 8
    for (int l = 0; l < 32; l++) {
        const int   orank = __shfl_sync(0xffffffffu, rank, l);
        const unsigned orow = __shfl_sync(0xffffffffu, myrow, l);
        if (orank < 32) rows[orank] = orow;
    }
    // sequential greedy scan, replicated on all lanes (cheap: K<=32 single-word ops)
    unsigned suppm = 0;
    for (int t = 0; t < K; t++) {
        if (!((suppm >> t) & 1u)) suppm |= rows[t];
    }

    const bool keep = act && !((suppm >> rank) & 1u);
    const unsigned km = __ballot_sync(0xffffffffu, keep);
    const int cnt = __popc(km);
    if (cnt == 0) return;
    const int leader = __ffs(km) - 1;
    int base = 0;
    if (lane == leader) base = atomicAdd(&d_img_cnt[b], cnt);
    base = __shfl_sync(0xffffffffu, base, leader);
    if (keep) {
        const int pos = base + __popc(km & ((1u << lane) - 1u));
        d_det_score[b][pos] = sc;
        d_det_box[b][pos] = bx;
        d_det_label[b][pos] = c + 1;
    }
}

// ---------------- kernel 2b: block NMS for K > 32 (suppression-mask method) ----------------
__global__ void nms_block_kernel() {
    const int bc = blockIdx.x;           // 0 .. B*NC-1
    const int K = d_cand_cnt[bc];
    if (K <= 32) return;                 // handled by warp kernel
    const int b = bc / NC;
    const int c = bc % NC;
    const int tid = threadIdx.x;         // NMSB_THREADS = 128

    __shared__ float  ss[MAXCAND];
    __shared__ int    sn[MAXCAND];
    __shared__ short  sslot[MAXCAND];
    __shared__ float4 sbox[MAXCAND];
    __shared__ unsigned mask[KMASK * NWM];
    __shared__ unsigned suppw[NWM];
    __shared__ unsigned char supp[MAXCAND];   // fallback path only

    int P = 1;
    while (P < K) P <<= 1;   // P <= 1024

    for (int i = tid; i < P; i += NMSB_THREADS) {
        if (i < K) {
            ss[i] = d_cand_score[b][c][i];
            sn[i] = d_cand_n[b][c][i];
            sbox[i] = d_cand_box[b][c][i];
        } else {
            ss[i] = -INFINITY;
            sn[i] = 0x7fffffff;
        }
        sslot[i] = (short)i;
    }
    __syncthreads();

    // bitonic sort: score desc, proposal-index asc
    for (int k = 2; k <= P; k <<= 1) {
        for (int j = k >> 1; j > 0; j >>= 1) {
            for (int i = tid; i < P; i += NMSB_THREADS) {
                const int ixj = i ^ j;
                if (ixj > i) {
                    const float a = ss[i], bb = ss[ixj];
                    const int   na = sn[i], nb = sn[ixj];
                    const bool i_after = (a < bb) || (a == bb && na > nb);
                    const bool dirAsc = ((i & k) == 0);
                    if (i_after == dirAsc) {
                        ss[i] = bb;  ss[ixj] = a;
                        sn[i] = nb;  sn[ixj] = na;
                        const short t = sslot[i]; sslot[i] = sslot[ixj]; sslot[ixj] = t;
                    }
                }
            }
            __syncthreads();
        }
    }

    if (K <= KMASK) {
        // ---- suppression-mask path: no per-round barriers ----
        const int nw = (K + 31) >> 5;
        for (int i = tid; i < K; i += NMSB_THREADS) {
            const float4 A = sbox[sslot[i]];
            const float areaA = (A.z - A.x + 1.0f) * (A.w - A.y + 1.0f);
            for (int w = 0; w < nw; w++) {
                unsigned m = 0;
                const int jbase = w << 5;
                const int jend = min(jbase + 32, K);
                for (int j = max(jbase, i + 1); j < jend; j++) {
                    const float4 Bx = sbox[sslot[j]];
                    const float iw = fmaxf(fminf(A.z, Bx.z) - fmaxf(A.x, Bx.x) + 1.0f, 0.0f);
                    const float ih = fmaxf(fminf(A.w, Bx.w) - fmaxf(A.y, Bx.y) + 1.0f, 0.0f);
                    const float inter = iw * ih;
                    const float areaB = (Bx.z - Bx.x + 1.0f) * (Bx.w - Bx.y + 1.0f);
                    const float iou = inter / (areaA + areaB - inter);
                    if (iou > NMS_TH) m |= 1u << (j & 31);
                }
                mask[i * NWM + w] = m;
            }
        }
        __syncthreads();

        // sequential greedy scan by warp 0: lane w owns suppression word w
        if (tid < 32) {
            unsigned sw = 0;
            for (int i = 0; i < K; i++) {
                const unsigned bit = (__shfl_sync(0xffffffffu, sw, i >> 5) >> (i & 31)) & 1u;
                if (!bit && tid < nw) sw |= mask[i * NWM + tid];
            }
            if (tid < nw) suppw[tid] = sw;
        }
        __syncthreads();

        for (int i = tid; i < K; i += NMSB_THREADS) {
            if (!((suppw[i >> 5] >> (i & 31)) & 1u)) {
                const int pos = atomicAdd(&d_img_cnt[b], 1);
                d_det_score[b][pos] = ss[i];
                d_det_box[b][pos] = sbox[sslot[i]];
                d_det_label[b][pos] = c + 1;
            }
        }
        return;
    }

    // ---- fallback greedy loop (K > KMASK; not expected in practice) ----
    for (int i = tid; i < P; i += NMSB_THREADS) supp[i] = (i >= K);
    __syncthreads();
    for (int i = 0; i < K; i++) {
        __syncthreads();
        if (supp[i]) continue;
        const float4 A = sbox[sslot[i]];
        const float areaA = (A.z - A.x + 1.0f) * (A.w - A.y + 1.0f);
        for (int j = i + 1 + tid; j < K; j += NMSB_THREADS) {
            if (supp[j]) continue;
            const float4 Bx = sbox[sslot[j]];
            const float iw = fmaxf(fminf(A.z, Bx.z) - fmaxf(A.x, Bx.x) + 1.0f, 0.0f);
            const float ih = fmaxf(fminf(A.w, Bx.w) - fmaxf(A.y, Bx.y) + 1.0f, 0.0f);
            const float inter = iw * ih;
            const float areaB = (Bx.z - Bx.x + 1.0f) * (Bx.w - Bx.y + 1.0f);
            const float iou = inter / (areaA + areaB - inter);
            if (iou > NMS_TH) supp[j] = 1;
        }
    }
    __syncthreads();
    for (int i = tid; i < K; i += NMSB_THREADS) {
        if (!supp[i]) {
            const int pos = atomicAdd(&d_img_cnt[b], 1);
            d_det_score[b][pos] = ss[i];
            d_det_box[b][pos] = sbox[sslot[i]];
            d_det_label[b][pos] = c + 1;
        }
    }
}

// ---------------- kernel 3: per-image top-100 via radix select + tiny sort ----------------
__global__ void topk_kernel(float* __restrict__ out) {
    const int b = blockIdx.x;
    const int tid = threadIdx.x;     // 1024
    const int M = d_img_cnt[b];

    float* detOut = out + (size_t)b * DETS * 5;
    float* labOut = out + (size_t)Bn * DETS * 5 + (size_t)b * DETS;
    float* valOut = out + (size_t)Bn * DETS * 5 + (size_t)Bn * DETS + (size_t)b * DETS;

    __shared__ int hist[256];
    __shared__ unsigned s_prefix;
    __shared__ int s_rank;
    __shared__ int s_cnt;
    __shared__ unsigned long long keys[GCAP];
    __shared__ unsigned sbits[SCACHE];

    const bool cached = (M <= SCACHE);
    if (cached) {
        for (int i = tid; i < M; i += 1024)
            sbits[i] = __float_as_uint(d_det_score[b][i]);
        __syncthreads();
    }

    unsigned T = 0u;
    if (M >= DETS) {
        if (tid == 0) { s_prefix = 0u; s_rank = DETS; }
        __syncthreads();
        for (int shift = 24; shift >= 0; shift -= 8) {
            for (int i = tid; i < 256; i += 1024) hist[i] = 0;
            __syncthreads();
            const unsigned pfx = s_prefix;
            const unsigned hmask = (shift == 24) ? 0u : (0xffffffffu << (shift + 8));
            for (int i = tid; i < M; i += 1024) {
                const unsigned bits = cached ? sbits[i]
                                             : __float_as_uint(d_det_score[b][i]);
                if ((bits & hmask) == (pfx & hmask))
                    atomicAdd(&hist[(bits >> shift) & 255], 1);
            }
            __syncthreads();
            if (tid == 0) {
                int cum = 0, rank = s_rank, dsel = 0;
                for (int d = 255; d >= 0; d--) {
                    if (cum + hist[d] >= rank) { dsel = d; s_rank = rank - cum; break; }
                    cum += hist[d];
                }
                s_prefix |= (unsigned)dsel << shift;
            }
            __syncthreads();
        }
        T = s_prefix;
    }

    if (tid == 0) s_cnt = 0;
    __syncthreads();
    for (int i = tid; i < M; i += 1024) {
        const unsigned bits = cached ? sbits[i] : __float_as_uint(d_det_score[b][i]);
        if (bits >= T) {
            const int p = atomicAdd(&s_cnt, 1);
            if (p < GCAP)
                keys[p] = ((unsigned long long)bits << 32) |
                          (unsigned)(0x7fffffff - i);
        }
    }
    __syncthreads();
    const int cnt = (s_cnt < GCAP) ? s_cnt : GCAP;

    int P = 128;
    while (P < cnt) P <<= 1;
    for (int i = cnt + tid; i < P; i += 1024) keys[i] = 0ull;
    __syncthreads();

    for (int k = 2; k <= P; k <<= 1) {
        for (int j = k >> 1; j > 0; j >>= 1) {
            for (int i = tid; i < P; i += 1024) {
                const int ixj = i ^ j;
                if (ixj > i) {
                    const unsigned long long a = keys[i], c = keys[ixj];
                    const bool descBlock = ((i & k) == 0);
                    if (descBlock ? (a < c) : (a > c)) {
                        keys[i] = c; keys[ixj] = a;
                    }
                }
            }
            __syncthreads();
        }
    }

    if (tid < DETS) {
        const unsigned long long key = keys[tid];
        if (tid < cnt && key != 0ull) {
            const int idx = 0x7fffffff - (int)(unsigned)(key & 0xffffffffull);
            const float score = __uint_as_float((unsigned)(key >> 32));
            const float4 bx = d_det_box[b][idx];
            detOut[tid * 5 + 0] = bx.x;
            detOut[tid * 5 + 1] = bx.y;
            detOut[tid * 5 + 2] = bx.z;
            detOut[tid * 5 + 3] = bx.w;
            detOut[tid * 5 + 4] = score;
            labOut[tid] = (float)d_det_label[b][idx];
            valOut[tid] = 1.0f;
        } else {
            detOut[tid * 5 + 0] = 0.0f;
            detOut[tid * 5 + 1] = 0.0f;
            detOut[tid * 5 + 2] = 0.0f;
            detOut[tid * 5 + 3] = 0.0f;
            detOut[tid * 5 + 4] = 0.0f;
            labOut[tid] = 0.0f;
            valOut[tid] = 0.0f;
        }
    }
}

// ---------------- launch ----------------
extern "C" void kernel_launch(void* const* d_in, const int* in_sizes, int n_in,
                              void* d_out, int out_size) {
    const float* logits = nullptr;
    const float* boxreg = nullptr;
    const float* props  = nullptr;
    for (int i = 0; i < n_in; i++) {
        if (in_sizes[i] == Bn * Nn * Cn)          logits = (const float*)d_in[i];
        else if (in_sizes[i] == Bn * Nn * 4 * Cn) boxreg = (const float*)d_in[i];
        else if (in_sizes[i] == Bn * Nn * 4)      props = (const float*)d_in[i];
    }
    float* out = (float*)d_out;

    zero_counters_kernel<<<(Bn * NC + 255) / 256, 256>>>();
    softmax_gather_kernel<<<(Bn * Nn) / ROWS_PER_CTA, 32 * ROWS_PER_CTA>>>(logits, boxreg, props);
    nms_warp_kernel<<<(Bn * NC + 7) / 8, 256>>>();
    nms_block_kernel<<<Bn * NC, NMSB_THREADS>>>();
    topk_kernel<<<Bn, 1024>>>(out);
}

// round 12
// speedup vs baseline: 1.2703x; 1.1270x over previous
#include <cuda_runtime.h>
#include <math.h>

#define Bn 32
#define Nn 1000
#define Cn 105
#define NC 104            // classes 1..104
#define SCORE_TH 0.05f
#define NMS_TH 0.5f
#define DETS 100
#define IMG_W 1333.0f
#define IMG_H 800.0f
#define BBOX_CLIP 4.135166556742356f   // log(1000/16)
#define MAXCAND 1024                   // per (image,class) candidate cap; K <= 1000
#define GCAP 512                       // gather capacity for final small sort (pow2)
#define ROWS_PER_CTA 8                 // warps per CTA in softmax kernel
#define SCACHE 6144                    // shared score-bit cache in topk
#define AMB_BAND 1e-5f                 // threshold ambiguity band for fast-exp guard
#define KMASK 320                      // rank/mask NMS path limit
#define NWM 10                         // mask words per row (KMASK/32)
#define NMSM_THREADS 256               // mid NMS thread count
#define NMSB_THREADS 128               // big (fallback) NMS thread count

// ---------------- scratch (device globals; no allocation allowed) ----------------
__device__ float  d_cand_score[Bn][NC][Nn];
__device__ float4 d_cand_box[Bn][NC][Nn];
__device__ int    d_cand_n[Bn][NC][Nn];
__device__ int    d_cand_cnt[Bn * NC];

__device__ float  d_det_score[Bn][NC * Nn];
__device__ float4 d_det_box[Bn][NC * Nn];
__device__ int    d_det_label[Bn][NC * Nn];
__device__ int    d_img_cnt[Bn];

// ---------------- kernel 0: zero counters (graph-replay safe) ----------------
__global__ void zero_counters_kernel() {
    int i = blockIdx.x * blockDim.x + threadIdx.x;
    if (i < Bn * NC) d_cand_cnt[i] = 0;
    if (i < Bn) d_img_cnt[i] = 0;
}

// ---------------- kernel 1: warp-per-row softmax + threshold + decode ----------------
__global__ void softmax_gather_kernel(const float* __restrict__ logits,
                                      const float* __restrict__ boxreg,
                                      const float* __restrict__ props) {
    const int wid = threadIdx.x >> 5;
    const int lane = threadIdx.x & 31;
    const int row = blockIdx.x * ROWS_PER_CTA + wid;   // grid = B*N/8 = 4000
    const int b = row / Nn;
    const int n = row % Nn;

    const float* L = logits + (size_t)row * Cn;

    float l[4];
    #pragma unroll
    for (int q = 0; q < 4; q++) {
        const int j = lane + 32 * q;
        l[q] = (j < Cn) ? L[j] : -INFINITY;
    }

    float mx = fmaxf(fmaxf(l[0], l[1]), fmaxf(l[2], l[3]));
    #pragma unroll
    for (int o = 16; o > 0; o >>= 1) mx = fmaxf(mx, __shfl_xor_sync(0xffffffffu, mx, o));

    float eh[4];
    float s = 0.0f;
    #pragma unroll
    for (int q = 0; q < 4; q++) {
        const int j = lane + 32 * q;
        eh[q] = (j < Cn) ? __expf(l[q] - mx) : 0.0f;
        s += eh[q];
    }
    #pragma unroll
    for (int o = 16; o > 0; o >>= 1) s += __shfl_xor_sync(0xffffffffu, s, o);
    float inv_s = 1.0f / s;

    float ph[4];
    bool amb = false;
    #pragma unroll
    for (int q = 0; q < 4; q++) {
        const int j = lane + 32 * q;
        ph[q] = eh[q] * inv_s;
        if (j >= 1 && j < Cn && fabsf(ph[q] - SCORE_TH) < AMB_BAND) amb = true;
    }
    bool precise_row = false;
    if (__ballot_sync(0xffffffffu, amb)) {
        float sp = 0.0f;
        #pragma unroll
        for (int q = 0; q < 4; q++) {
            const int j = lane + 32 * q;
            eh[q] = (j < Cn) ? expf(l[q] - mx) : 0.0f;
            sp += eh[q];
        }
        #pragma unroll
        for (int o = 16; o > 0; o >>= 1) sp += __shfl_xor_sync(0xffffffffu, sp, o);
        inv_s = 1.0f / sp;
        #pragma unroll
        for (int q = 0; q < 4; q++) ph[q] = eh[q] * inv_s;
        precise_row = true;
    }

    const float4 pr = *(const float4*)(props + (size_t)row * 4);
    const float w  = pr.z - pr.x + 1.0f;
    const float h  = pr.w - pr.y + 1.0f;
    const float cx = pr.x + 0.5f * w;
    const float cy = pr.y + 0.5f * h;

    #pragma unroll
    for (int q = 0; q < 4; q++) {
        const int j = lane + 32 * q;
        if (j >= 1 && j < Cn && ph[q] > SCORE_TH) {
            const float p_store = precise_row ? ph[q] : expf(l[q] - mx) * inv_s;

            const float4 r = *(const float4*)(boxreg + ((size_t)row * Cn + j) * 4);
            const float dx = r.x / 10.0f;
            const float dy = r.y / 10.0f;
            const float dw = fminf(r.z / 5.0f, BBOX_CLIP);
            const float dh = fminf(r.w / 5.0f, BBOX_CLIP);
            const float pcx = dx * w + cx;
            const float pcy = dy * h + cy;
            const float pw = expf(dw) * w;
            const float ph2 = expf(dh) * h;
            float4 box;
            box.x = fminf(fmaxf(pcx - 0.5f * pw, 0.0f), IMG_W - 1.0f);
            box.y = fminf(fmaxf(pcy - 0.5f * ph2, 0.0f), IMG_H - 1.0f);
            box.z = fminf(fmaxf(pcx + 0.5f * pw - 1.0f, 0.0f), IMG_W - 1.0f);
            box.w = fminf(fmaxf(pcy + 0.5f * ph2 - 1.0f, 0.0f), IMG_H - 1.0f);

            const int c = j - 1;
            const int slot = atomicAdd(&d_cand_cnt[b * NC + c], 1);
            d_cand_score[b][c][slot] = p_store;
            d_cand_n[b][c][slot] = n;
            d_cand_box[b][c][slot] = box;
        }
    }
}

// ---------------- kernel 2a: warp-level NMS for K <= 32 ----------------
__global__ void nms_warp_kernel() {
    const int wid = threadIdx.x >> 5;
    const int lane = threadIdx.x & 31;
    const int cell = blockIdx.x * 8 + wid;
    if (cell >= Bn * NC) return;
    const int K = d_cand_cnt[cell];
    if (K == 0 || K > 32) return;
    const int b = cell / NC;
    const int c = cell % NC;

    if (K == 1) {
        if (lane == 0) {
            const int pos = atomicAdd(&d_img_cnt[b], 1);
            d_det_score[b][pos] = d_cand_score[b][c][0];
            d_det_box[b][pos] = d_cand_box[b][c][0];
            d_det_label[b][pos] = c + 1;
        }
        return;
    }

    const bool act = lane < K;
    const float sc = act ? d_cand_score[b][c][lane] : -INFINITY;
    const int   nn = act ? d_cand_n[b][c][lane] : 0x7fffffff;
    float4 bx = make_float4(0.0f, 0.0f, 0.0f, 0.0f);
    if (act) bx = d_cand_box[b][c][lane];

    // rank = #elements strictly better (score desc, proposal-index asc)
    int rank = 0;
    #pragma unroll 8
    for (int l = 0; l < 32; l++) {
        const float osc = __shfl_sync(0xffffffffu, sc, l);
        const int   onn = __shfl_sync(0xffffffffu, nn, l);
        if (osc > sc || (osc == sc && onn < nn)) rank++;
    }

    const float area = (bx.z - bx.x + 1.0f) * (bx.w - bx.y + 1.0f);

    // suppression bitmask over ranks: my row = ranks I would suppress (rank>mine, iou>th)
    unsigned myrow = 0;
    #pragma unroll 8
    for (int l = 0; l < 32; l++) {
        const int   orank = __shfl_sync(0xffffffffu, rank, l);
        const float ox1 = __shfl_sync(0xffffffffu, bx.x, l);
        const float oy1 = __shfl_sync(0xffffffffu, bx.y, l);
        const float ox2 = __shfl_sync(0xffffffffu, bx.z, l);
        const float oy2 = __shfl_sync(0xffffffffu, bx.w, l);
        const float oarea = __shfl_sync(0xffffffffu, area, l);
        const bool oact = (orank < K);
        if (act && oact && orank > rank) {
            const float iw = fmaxf(fminf(ox2, bx.z) - fmaxf(ox1, bx.x) + 1.0f, 0.0f);
            const float ih = fmaxf(fminf(oy2, bx.w) - fmaxf(oy1, bx.y) + 1.0f, 0.0f);
            const float inter = iw * ih;
            const float iou = inter / (area + oarea - inter);
            if (iou > NMS_TH) myrow |= 1u << orank;
        }
    }
    // all lanes build rank->row table via shuffle
    unsigned rows[32];
    #pragma unroll 8
    for (int l = 0; l < 32; l++) {
        const int   orank = __shfl_sync(0xffffffffu, rank, l);
        const unsigned orow = __shfl_sync(0xffffffffu, myrow, l);
        if (orank < 32) rows[orank] = orow;
    }
    // sequential greedy scan, replicated on all lanes
    unsigned suppm = 0;
    for (int t = 0; t < K; t++) {
        if (!((suppm >> t) & 1u)) suppm |= rows[t];
    }

    const bool keep = act && !((suppm >> rank) & 1u);
    const unsigned km = __ballot_sync(0xffffffffu, keep);
    const int cnt = __popc(km);
    if (cnt == 0) return;
    const int leader = __ffs(km) - 1;
    int base = 0;
    if (lane == leader) base = atomicAdd(&d_img_cnt[b], cnt);
    base = __shfl_sync(0xffffffffu, base, leader);
    if (keep) {
        const int pos = base + __popc(km & ((1u << lane) - 1u));
        d_det_score[b][pos] = sc;
        d_det_box[b][pos] = bx;
        d_det_label[b][pos] = c + 1;
    }
}

// ---------------- kernel 2b: rank+mask NMS for 32 < K <= KMASK (no sort) ----------------
__global__ void nms_mid_kernel() {
    const int bc = blockIdx.x;           // 0 .. B*NC-1
    const int K = d_cand_cnt[bc];
    if (K <= 32 || K > KMASK) return;
    const int b = bc / NC;
    const int c = bc % NC;
    const int tid = threadIdx.x;         // NMSM_THREADS = 256

    __shared__ unsigned long long skey[KMASK];
    __shared__ float4 sbox[KMASK];
    __shared__ short perm[KMASK];        // rank -> slot
    __shared__ short rnk[KMASK];         // slot -> rank
    __shared__ unsigned mask[KMASK * NWM];
    __shared__ unsigned suppw[NWM];

    // load; key = (score_bits << 32) | (0x7fffffff - n): bigger = earlier in greedy order
    for (int i = tid; i < K; i += NMSM_THREADS) {
        const unsigned sb = __float_as_uint(d_cand_score[b][c][i]);
        skey[i] = ((unsigned long long)sb << 32) |
                  (unsigned)(0x7fffffff - d_cand_n[b][c][i]);
        sbox[i] = d_cand_box[b][c][i];
    }
    __syncthreads();

    // rank by counting (keys unique: n unique per (b,c) cell); perfect scatter into perm
    for (int i = tid; i < K; i += NMSM_THREADS) {
        const unsigned long long me = skey[i];
        int r = 0;
        for (int j = 0; j < K; j++) r += (skey[j] > me);
        rnk[i] = (short)r;
        perm[r] = (short)i;
    }
    __syncthreads();

    const int nw = (K + 31) >> 5;
    // mask row r (rank order): bits j>r with IoU > threshold
    for (int r = tid; r < K; r += NMSM_THREADS) {
        const float4 A = sbox[perm[r]];
        const float areaA = (A.z - A.x + 1.0f) * (A.w - A.y + 1.0f);
        for (int w = 0; w < nw; w++) {
            unsigned m = 0;
            const int jbase = w << 5;
            const int jend = min(jbase + 32, K);
            for (int j = max(jbase, r + 1); j < jend; j++) {
                const float4 Bx = sbox[perm[j]];
                const float iw = fmaxf(fminf(A.z, Bx.z) - fmaxf(A.x, Bx.x) + 1.0f, 0.0f);
                const float ih = fmaxf(fminf(A.w, Bx.w) - fmaxf(A.y, Bx.y) + 1.0f, 0.0f);
                const float inter = iw * ih;
                const float areaB = (Bx.z - Bx.x + 1.0f) * (Bx.w - Bx.y + 1.0f);
                const float iou = inter / (areaA + areaB - inter);
                if (iou > NMS_TH) m |= 1u << (j & 31);
            }
            mask[r * NWM + w] = m;
        }
    }
    __syncthreads();

    // sequential greedy scan by warp 0: lane w owns suppression word w
    if (tid < 32) {
        unsigned sw = 0;
        for (int i = 0; i < K; i++) {
            const unsigned bit = (__shfl_sync(0xffffffffu, sw, i >> 5) >> (i & 31)) & 1u;
            if (!bit && tid < nw) sw |= mask[i * NWM + tid];
        }
        if (tid < nw) suppw[tid] = sw;
    }
    __syncthreads();

    for (int i = tid; i < K; i += NMSM_THREADS) {
        const int r = rnk[i];
        if (!((suppw[r >> 5] >> (r & 31)) & 1u)) {
            const int pos = atomicAdd(&d_img_cnt[b], 1);
            d_det_score[b][pos] = __uint_as_float((unsigned)(skey[i] >> 32));
            d_det_box[b][pos] = sbox[i];
            d_det_label[b][pos] = c + 1;
        }
    }
}

// ---------------- kernel 2c: fallback sort+greedy NMS for K > KMASK ----------------
__global__ void nms_big_kernel() {
    const int bc = blockIdx.x;
    const int K = d_cand_cnt[bc];
    if (K <= KMASK) return;
    const int b = bc / NC;
    const int c = bc % NC;
    const int tid = threadIdx.x;         // NMSB_THREADS = 128

    __shared__ float  ss[MAXCAND];
    __shared__ int    sn[MAXCAND];
    __shared__ short  sslot[MAXCAND];
    __shared__ float4 sbox[MAXCAND];
    __shared__ unsigned char supp[MAXCAND];

    int P = 1;
    while (P < K) P <<= 1;

    for (int i = tid; i < P; i += NMSB_THREADS) {
        if (i < K) {
            ss[i] = d_cand_score[b][c][i];
            sn[i] = d_cand_n[b][c][i];
            sbox[i] = d_cand_box[b][c][i];
        } else {
            ss[i] = -INFINITY;
            sn[i] = 0x7fffffff;
        }
        sslot[i] = (short)i;
        supp[i] = (i >= K);
    }
    __syncthreads();

    for (int k = 2; k <= P; k <<= 1) {
        for (int j = k >> 1; j > 0; j >>= 1) {
            for (int i = tid; i < P; i += NMSB_THREADS) {
                const int ixj = i ^ j;
                if (ixj > i) {
                    const float a = ss[i], bb = ss[ixj];
                    const int   na = sn[i], nb = sn[ixj];
                    const bool i_after = (a < bb) || (a == bb && na > nb);
                    const bool dirAsc = ((i & k) == 0);
                    if (i_after == dirAsc) {
                        ss[i] = bb;  ss[ixj] = a;
                        sn[i] = nb;  sn[ixj] = na;
                        const short t = sslot[i]; sslot[i] = sslot[ixj]; sslot[ixj] = t;
                    }
                }
            }
            __syncthreads();
        }
    }

    for (int i = 0; i < K; i++) {
        __syncthreads();
        if (supp[i]) continue;
        const float4 A = sbox[sslot[i]];
        const float areaA = (A.z - A.x + 1.0f) * (A.w - A.y + 1.0f);
        for (int j = i + 1 + tid; j < K; j += NMSB_THREADS) {
            if (supp[j]) continue;
            const float4 Bx = sbox[sslot[j]];
            const float iw = fmaxf(fminf(A.z, Bx.z) - fmaxf(A.x, Bx.x) + 1.0f, 0.0f);
            const float ih = fmaxf(fminf(A.w, Bx.w) - fmaxf(A.y, Bx.y) + 1.0f, 0.0f);
            const float inter = iw * ih;
            const float areaB = (Bx.z - Bx.x + 1.0f) * (Bx.w - Bx.y + 1.0f);
            const float iou = inter / (areaA + areaB - inter);
            if (iou > NMS_TH) supp[j] = 1;
        }
    }
    __syncthreads();
    for (int i = tid; i < K; i += NMSB_THREADS) {
        if (!supp[i]) {
            const int pos = atomicAdd(&d_img_cnt[b], 1);
            d_det_score[b][pos] = ss[i];
            d_det_box[b][pos] = sbox[sslot[i]];
            d_det_label[b][pos] = c + 1;
        }
    }
}

// ---------------- kernel 3: per-image top-100 via radix select + tiny sort ----------------
__global__ void topk_kernel(float* __restrict__ out) {
    const int b = blockIdx.x;
    const int tid = threadIdx.x;     // 1024
    const int M = d_img_cnt[b];

    float* detOut = out + (size_t)b * DETS * 5;
    float* labOut = out + (size_t)Bn * DETS * 5 + (size_t)b * DETS;
    float* valOut = out + (size_t)Bn * DETS * 5 + (size_t)Bn * DETS + (size_t)b * DETS;

    __shared__ int hist[256];
    __shared__ unsigned s_prefix;
    __shared__ int s_rank;
    __shared__ int s_cnt;
    __shared__ unsigned long long keys[GCAP];
    __shared__ unsigned sbits[SCACHE];

    const bool cached = (M <= SCACHE);
    if (cached) {
        for (int i = tid; i < M; i += 1024)
            sbits[i] = __float_as_uint(d_det_score[b][i]);
        __syncthreads();
    }

    unsigned T = 0u;
    if (M >= DETS) {
        if (tid == 0) { s_prefix = 0u; s_rank = DETS; }
        __syncthreads();
        for (int shift = 24; shift >= 0; shift -= 8) {
            for (int i = tid; i < 256; i += 1024) hist[i] = 0;
            __syncthreads();
            const unsigned pfx = s_prefix;
            const unsigned hmask = (shift == 24) ? 0u : (0xffffffffu << (shift + 8));
            for (int i = tid; i < M; i += 1024) {
                const unsigned bits = cached ? sbits[i]
                                             : __float_as_uint(d_det_score[b][i]);
                if ((bits & hmask) == (pfx & hmask))
                    atomicAdd(&hist[(bits >> shift) & 255], 1);
            }
            __syncthreads();
            if (tid == 0) {
                int cum = 0, rank = s_rank, dsel = 0;
                for (int d = 255; d >= 0; d--) {
                    if (cum + hist[d] >= rank) { dsel = d; s_rank = rank - cum; break; }
                    cum += hist[d];
                }
                s_prefix |= (unsigned)dsel << shift;
            }
            __syncthreads();
        }
        T = s_prefix;
    }

    if (tid == 0) s_cnt = 0;
    __syncthreads();
    for (int i = tid; i < M; i += 1024) {
        const unsigned bits = cached ? sbits[i] : __float_as_uint(d_det_score[b][i]);
        if (bits >= T) {
            const int p = atomicAdd(&s_cnt, 1);
            if (p < GCAP)
                keys[p] = ((unsigned long long)bits << 32) |
                          (unsigned)(0x7fffffff - i);
        }
    }
    __syncthreads();
    const int cnt = (s_cnt < GCAP) ? s_cnt : GCAP;

    int P = 128;
    while (P < cnt) P <<= 1;
    for (int i = cnt + tid; i < P; i += 1024) keys[i] = 0ull;
    __syncthreads();

    for (int k = 2; k <= P; k <<= 1) {
        for (int j = k >> 1; j > 0; j >>= 1) {
            for (int i = tid; i < P; i += 1024) {
                const int ixj = i ^ j;
                if (ixj > i) {
                    const unsigned long long a = keys[i], c = keys[ixj];
                    const bool descBlock = ((i & k) == 0);
                    if (descBlock ? (a < c) : (a > c)) {
                        keys[i] = c; keys[ixj] = a;
                    }
                }
            }
            __syncthreads();
        }
    }

    if (tid < DETS) {
        const unsigned long long key = keys[tid];
        if (tid < cnt && key != 0ull) {
            const int idx = 0x7fffffff - (int)(unsigned)(key & 0xffffffffull);
            const float score = __uint_as_float((unsigned)(key >> 32));
            const float4 bx = d_det_box[b][idx];
            detOut[tid * 5 + 0] = bx.x;
            detOut[tid * 5 + 1] = bx.y;
            detOut[tid * 5 + 2] = bx.z;
            detOut[tid * 5 + 3] = bx.w;
            detOut[tid * 5 + 4] = score;
            labOut[tid] = (float)d_det_label[b][idx];
            valOut[tid] = 1.0f;
        } else {
            detOut[tid * 5 + 0] = 0.0f;
            detOut[tid * 5 + 1] = 0.0f;
            detOut[tid * 5 + 2] = 0.0f;
            detOut[tid * 5 + 3] = 0.0f;
            detOut[tid * 5 + 4] = 0.0f;
            labOut[tid] = 0.0f;
            valOut[tid] = 0.0f;
        }
    }
}

// ---------------- launch ----------------
extern "C" void kernel_launch(void* const* d_in, const int* in_sizes, int n_in,
                              void* d_out, int out_size) {
    const float* logits = nullptr;
    const float* boxreg = nullptr;
    const float* props  = nullptr;
    for (int i = 0; i < n_in; i++) {
        if (in_sizes[i] == Bn * Nn * Cn)          logits = (const float*)d_in[i];
        else if (in_sizes[i] == Bn * Nn * 4 * Cn) boxreg = (const float*)d_in[i];
        else if (in_sizes[i] == Bn * Nn * 4)      props = (const float*)d_in[i];
    }
    float* out = (float*)d_out;

    zero_counters_kernel<<<(Bn * NC + 255) / 256, 256>>>();
    softmax_gather_kernel<<<(Bn * Nn) / ROWS_PER_CTA, 32 * ROWS_PER_CTA>>>(logits, boxreg, props);
    nms_warp_kernel<<<(Bn * NC + 7) / 8, 256>>>();
    nms_mid_kernel<<<Bn * NC, NMSM_THREADS>>>();
    nms_big_kernel<<<Bn * NC, NMSB_THREADS>>>();
    topk_kernel<<<Bn, 1024>>>(out);
}

// round 13
// speedup vs baseline: 1.4044x; 1.1056x over previous
#include <cuda_runtime.h>
#include <math.h>

#define Bn 32
#define Nn 1000
#define Cn 105
#define NC 104            // classes 1..104
#define SCORE_TH 0.05f
#define NMS_TH 0.5f
#define DETS 100
#define IMG_W 1333.0f
#define IMG_H 800.0f
#define BBOX_CLIP 4.135166556742356f   // log(1000/16)
#define MAXCAND 1024                   // per (image,class) candidate cap; K <= 1000
#define GCAP 512                       // gather capacity for final small sort (pow2)
#define ROWS_PER_CTA 8                 // warps per CTA in softmax kernel
#define SCACHE 6144                    // shared score-bit cache in topk
#define AMB_BAND 1e-5f                 // threshold ambiguity band for fast-exp guard
#define KMASK 320                      // rank/mask NMS path limit
#define NWM 10                         // mask words per row (KMASK/32)
#define NMSM_THREADS 256               // mid NMS thread count
#define NMSB_THREADS 128               // big (fallback) NMS thread count

// ---------------- scratch (device globals; no allocation allowed) ----------------
__device__ float  d_cand_score[Bn][NC][Nn];
__device__ float4 d_cand_box[Bn][NC][Nn];
__device__ int    d_cand_n[Bn][NC][Nn];
__device__ int    d_cand_cnt[Bn * NC];

__device__ float  d_det_score[Bn][NC * Nn];
__device__ float4 d_det_box[Bn][NC * Nn];
__device__ int    d_det_label[Bn][NC * Nn];
__device__ int    d_img_cnt[Bn];

// ---------------- kernel 0: zero counters (graph-replay safe) ----------------
__global__ void zero_counters_kernel() {
    int i = blockIdx.x * blockDim.x + threadIdx.x;
    if (i < Bn * NC) d_cand_cnt[i] = 0;
    if (i < Bn) d_img_cnt[i] = 0;
}

// ---------------- kernel 1: warp-per-row softmax + threshold + decode ----------------
__global__ void softmax_gather_kernel(const float* __restrict__ logits,
                                      const float* __restrict__ boxreg,
                                      const float* __restrict__ props) {
    const int wid = threadIdx.x >> 5;
    const int lane = threadIdx.x & 31;
    const int row = blockIdx.x * ROWS_PER_CTA + wid;   // grid = B*N/8 = 4000
    const int b = row / Nn;
    const int n = row % Nn;

    const float* L = logits + (size_t)row * Cn;

    float l[4];
    #pragma unroll
    for (int q = 0; q < 4; q++) {
        const int j = lane + 32 * q;
        l[q] = (j < Cn) ? L[j] : -INFINITY;
    }

    float mx = fmaxf(fmaxf(l[0], l[1]), fmaxf(l[2], l[3]));
    #pragma unroll
    for (int o = 16; o > 0; o >>= 1) mx = fmaxf(mx, __shfl_xor_sync(0xffffffffu, mx, o));

    float eh[4];
    float s = 0.0f;
    #pragma unroll
    for (int q = 0; q < 4; q++) {
        const int j = lane + 32 * q;
        eh[q] = (j < Cn) ? __expf(l[q] - mx) : 0.0f;
        s += eh[q];
    }
    #pragma unroll
    for (int o = 16; o > 0; o >>= 1) s += __shfl_xor_sync(0xffffffffu, s, o);
    float inv_s = 1.0f / s;

    float ph[4];
    bool amb = false;
    #pragma unroll
    for (int q = 0; q < 4; q++) {
        const int j = lane + 32 * q;
        ph[q] = eh[q] * inv_s;
        if (j >= 1 && j < Cn && fabsf(ph[q] - SCORE_TH) < AMB_BAND) amb = true;
    }
    bool precise_row = false;
    if (__ballot_sync(0xffffffffu, amb)) {
        float sp = 0.0f;
        #pragma unroll
        for (int q = 0; q < 4; q++) {
            const int j = lane + 32 * q;
            eh[q] = (j < Cn) ? expf(l[q] - mx) : 0.0f;
            sp += eh[q];
        }
        #pragma unroll
        for (int o = 16; o > 0; o >>= 1) sp += __shfl_xor_sync(0xffffffffu, sp, o);
        inv_s = 1.0f / sp;
        #pragma unroll
        for (int q = 0; q < 4; q++) ph[q] = eh[q] * inv_s;
        precise_row = true;
    }

    const float4 pr = *(const float4*)(props + (size_t)row * 4);
    const float w  = pr.z - pr.x + 1.0f;
    const float h  = pr.w - pr.y + 1.0f;
    const float cx = pr.x + 0.5f * w;
    const float cy = pr.y + 0.5f * h;

    #pragma unroll
    for (int q = 0; q < 4; q++) {
        const int j = lane + 32 * q;
        if (j >= 1 && j < Cn && ph[q] > SCORE_TH) {
            const float p_store = precise_row ? ph[q] : expf(l[q] - mx) * inv_s;

            const float4 r = *(const float4*)(boxreg + ((size_t)row * Cn + j) * 4);
            const float dx = r.x / 10.0f;
            const float dy = r.y / 10.0f;
            const float dw = fminf(r.z / 5.0f, BBOX_CLIP);
            const float dh = fminf(r.w / 5.0f, BBOX_CLIP);
            const float pcx = dx * w + cx;
            const float pcy = dy * h + cy;
            const float pw = expf(dw) * w;
            const float ph2 = expf(dh) * h;
            float4 box;
            box.x = fminf(fmaxf(pcx - 0.5f * pw, 0.0f), IMG_W - 1.0f);
            box.y = fminf(fmaxf(pcy - 0.5f * ph2, 0.0f), IMG_H - 1.0f);
            box.z = fminf(fmaxf(pcx + 0.5f * pw - 1.0f, 0.0f), IMG_W - 1.0f);
            box.w = fminf(fmaxf(pcy + 0.5f * ph2 - 1.0f, 0.0f), IMG_H - 1.0f);

            const int c = j - 1;
            const int slot = atomicAdd(&d_cand_cnt[b * NC + c], 1);
            d_cand_score[b][c][slot] = p_store;
            d_cand_n[b][c][slot] = n;
            d_cand_box[b][c][slot] = box;
        }
    }
}

// ---------------- kernel 2a: warp-level NMS for K <= 32 ----------------
__global__ void nms_warp_kernel() {
    const int wid = threadIdx.x >> 5;
    const int lane = threadIdx.x & 31;
    const int cell = blockIdx.x * 8 + wid;
    if (cell >= Bn * NC) return;
    const int K = d_cand_cnt[cell];
    if (K == 0 || K > 32) return;
    const int b = cell / NC;
    const int c = cell % NC;

    if (K == 1) {
        if (lane == 0) {
            const int pos = atomicAdd(&d_img_cnt[b], 1);
            d_det_score[b][pos] = d_cand_score[b][c][0];
            d_det_box[b][pos] = d_cand_box[b][c][0];
            d_det_label[b][pos] = c + 1;
        }
        return;
    }

    const bool act = lane < K;
    const float sc = act ? d_cand_score[b][c][lane] : -INFINITY;
    const int   nn = act ? d_cand_n[b][c][lane] : 0x7fffffff;
    float4 bx = make_float4(0.0f, 0.0f, 0.0f, 0.0f);
    if (act) bx = d_cand_box[b][c][lane];

    // rank = #elements strictly better (score desc, proposal-index asc)
    int rank = 0;
    #pragma unroll 8
    for (int l = 0; l < 32; l++) {
        const float osc = __shfl_sync(0xffffffffu, sc, l);
        const int   onn = __shfl_sync(0xffffffffu, nn, l);
        if (osc > sc || (osc == sc && onn < nn)) rank++;
    }

    const float area = (bx.z - bx.x + 1.0f) * (bx.w - bx.y + 1.0f);

    // suppression bitmask over ranks
    unsigned myrow = 0;
    #pragma unroll 8
    for (int l = 0; l < 32; l++) {
        const int   orank = __shfl_sync(0xffffffffu, rank, l);
        const float ox1 = __shfl_sync(0xffffffffu, bx.x, l);
        const float oy1 = __shfl_sync(0xffffffffu, bx.y, l);
        const float ox2 = __shfl_sync(0xffffffffu, bx.z, l);
        const float oy2 = __shfl_sync(0xffffffffu, bx.w, l);
        const float oarea = __shfl_sync(0xffffffffu, area, l);
        const bool oact = (orank < K);
        if (act && oact && orank > rank) {
            const float iw = fmaxf(fminf(ox2, bx.z) - fmaxf(ox1, bx.x) + 1.0f, 0.0f);
            const float ih = fmaxf(fminf(oy2, bx.w) - fmaxf(oy1, bx.y) + 1.0f, 0.0f);
            const float inter = iw * ih;
            const float iou = inter / (area + oarea - inter);
            if (iou > NMS_TH) myrow |= 1u << orank;
        }
    }
    // rank->row table via shuffle
    unsigned rows[32];
    #pragma unroll 8
    for (int l = 0; l < 32; l++) {
        const int   orank = __shfl_sync(0xffffffffu, rank, l);
        const unsigned orow = __shfl_sync(0xffffffffu, myrow, l);
        if (orank < 32) rows[orank] = orow;
    }
    // sequential greedy scan, replicated
    unsigned suppm = 0;
    for (int t = 0; t < K; t++) {
        if (!((suppm >> t) & 1u)) suppm |= rows[t];
    }

    const bool keep = act && !((suppm >> rank) & 1u);
    const unsigned km = __ballot_sync(0xffffffffu, keep);
    const int cnt = __popc(km);
    if (cnt == 0) return;
    const int leader = __ffs(km) - 1;
    int base = 0;
    if (lane == leader) base = atomicAdd(&d_img_cnt[b], cnt);
    base = __shfl_sync(0xffffffffu, base, leader);
    if (keep) {
        const int pos = base + __popc(km & ((1u << lane) - 1u));
        d_det_score[b][pos] = sc;
        d_det_box[b][pos] = bx;
        d_det_label[b][pos] = c + 1;
    }
}

// ---------------- kernel 2b: rank+mask NMS for 32 < K <= KMASK (no sort, balanced) ----------------
__global__ void nms_mid_kernel() {
    const int bc = blockIdx.x;           // 0 .. B*NC-1
    const int K = d_cand_cnt[bc];
    if (K <= 32 || K > KMASK) return;
    const int b = bc / NC;
    const int c = bc % NC;
    const int tid = threadIdx.x;         // NMSM_THREADS = 256

    __shared__ unsigned long long skey[KMASK];
    __shared__ float4 sbox[KMASK];       // slot order
    __shared__ float4 sbox2[KMASK];      // rank order
    __shared__ float  sarea[KMASK];      // rank order
    __shared__ short perm[KMASK];        // rank -> slot
    __shared__ short rnk[KMASK];         // slot -> rank
    __shared__ unsigned mask[KMASK * NWM];
    __shared__ unsigned suppw[NWM];

    // load; key = (score_bits << 32) | (0x7fffffff - n): bigger = earlier in greedy order
    for (int i = tid; i < K; i += NMSM_THREADS) {
        const unsigned sb = __float_as_uint(d_cand_score[b][c][i]);
        skey[i] = ((unsigned long long)sb << 32) |
                  (unsigned)(0x7fffffff - d_cand_n[b][c][i]);
        sbox[i] = d_cand_box[b][c][i];
    }
    __syncthreads();

    // rank by counting (keys unique); perfect scatter into perm
    for (int i = tid; i < K; i += NMSM_THREADS) {
        const unsigned long long me = skey[i];
        int r = 0;
        for (int j = 0; j < K; j++) r += (skey[j] > me);
        rnk[i] = (short)r;
        perm[r] = (short)i;
    }
    __syncthreads();

    // stage boxes + areas in rank order (kills indirection in hot loop)
    for (int r = tid; r < K; r += NMSM_THREADS) {
        const float4 A = sbox[perm[r]];
        sbox2[r] = A;
        sarea[r] = (A.z - A.x + 1.0f) * (A.w - A.y + 1.0f);
    }
    __syncthreads();

    const int nw = (K + 31) >> 5;
    // balanced mask build: one work item = one (row, word) pair, <= 32 IoUs each
    const int totalWork = K * nw;
    for (int t = tid; t < totalWork; t += NMSM_THREADS) {
        const int r = t / nw;
        const int w = t - r * nw;
        const int jbase = w << 5;
        const int jend = min(jbase + 32, K);
        unsigned m = 0;
        if (jend > r + 1) {              // word has entries above the diagonal
            const float4 A = sbox2[r];
            const float areaA = sarea[r];
            for (int j = max(jbase, r + 1); j < jend; j++) {
                const float4 Bx = sbox2[j];
                const float iw = fmaxf(fminf(A.z, Bx.z) - fmaxf(A.x, Bx.x) + 1.0f, 0.0f);
                const float ih = fmaxf(fminf(A.w, Bx.w) - fmaxf(A.y, Bx.y) + 1.0f, 0.0f);
                const float inter = iw * ih;
                const float iou = inter / (areaA + sarea[j] - inter);
                if (iou > NMS_TH) m |= 1u << (j & 31);
            }
        }
        mask[r * NWM + w] = m;
    }
    __syncthreads();

    // sequential greedy scan by warp 0: lane w owns suppression word w
    if (tid < 32) {
        unsigned sw = 0;
        for (int i = 0; i < K; i++) {
            const unsigned bit = (__shfl_sync(0xffffffffu, sw, i >> 5) >> (i & 31)) & 1u;
            if (!bit && tid < nw) sw |= mask[i * NWM + tid];
        }
        if (tid < nw) suppw[tid] = sw;
    }
    __syncthreads();

    for (int i = tid; i < K; i += NMSM_THREADS) {
        const int r = rnk[i];
        if (!((suppw[r >> 5] >> (r & 31)) & 1u)) {
            const int pos = atomicAdd(&d_img_cnt[b], 1);
            d_det_score[b][pos] = __uint_as_float((unsigned)(skey[i] >> 32));
            d_det_box[b][pos] = sbox[i];
            d_det_label[b][pos] = c + 1;
        }
    }
}

// ---------------- kernel 2c: fallback sort+greedy NMS for K > KMASK ----------------
__global__ void nms_big_kernel() {
    const int bc = blockIdx.x;
    const int K = d_cand_cnt[bc];
    if (K <= KMASK) return;
    const int b = bc / NC;
    const int c = bc % NC;
    const int tid = threadIdx.x;         // NMSB_THREADS = 128

    __shared__ float  ss[MAXCAND];
    __shared__ int    sn[MAXCAND];
    __shared__ short  sslot[MAXCAND];
    __shared__ float4 sbox[MAXCAND];
    __shared__ unsigned char supp[MAXCAND];

    int P = 1;
    while (P < K) P <<= 1;

    for (int i = tid; i < P; i += NMSB_THREADS) {
        if (i < K) {
            ss[i] = d_cand_score[b][c][i];
            sn[i] = d_cand_n[b][c][i];
            sbox[i] = d_cand_box[b][c][i];
        } else {
            ss[i] = -INFINITY;
            sn[i] = 0x7fffffff;
        }
        sslot[i] = (short)i;
        supp[i] = (i >= K);
    }
    __syncthreads();

    for (int k = 2; k <= P; k <<= 1) {
        for (int j = k >> 1; j > 0; j >>= 1) {
            for (int i = tid; i < P; i += NMSB_THREADS) {
                const int ixj = i ^ j;
                if (ixj > i) {
                    const float a = ss[i], bb = ss[ixj];
                    const int   na = sn[i], nb = sn[ixj];
                    const bool i_after = (a < bb) || (a == bb && na > nb);
                    const bool dirAsc = ((i & k) == 0);
                    if (i_after == dirAsc) {
                        ss[i] = bb;  ss[ixj] = a;
                        sn[i] = nb;  sn[ixj] = na;
                        const short t = sslot[i]; sslot[i] = sslot[ixj]; sslot[ixj] = t;
                    }
                }
            }
            __syncthreads();
        }
    }

    for (int i = 0; i < K; i++) {
        __syncthreads();
        if (supp[i]) continue;
        const float4 A = sbox[sslot[i]];
        const float areaA = (A.z - A.x + 1.0f) * (A.w - A.y + 1.0f);
        for (int j = i + 1 + tid; j < K; j += NMSB_THREADS) {
            if (supp[j]) continue;
            const float4 Bx = sbox[sslot[j]];
            const float iw = fmaxf(fminf(A.z, Bx.z) - fmaxf(A.x, Bx.x) + 1.0f, 0.0f);
            const float ih = fmaxf(fminf(A.w, Bx.w) - fmaxf(A.y, Bx.y) + 1.0f, 0.0f);
            const float inter = iw * ih;
            const float areaB = (Bx.z - Bx.x + 1.0f) * (Bx.w - Bx.y + 1.0f);
            const float iou = inter / (areaA + areaB - inter);
            if (iou > NMS_TH) supp[j] = 1;
        }
    }
    __syncthreads();
    for (int i = tid; i < K; i += NMSB_THREADS) {
        if (!supp[i]) {
            const int pos = atomicAdd(&d_img_cnt[b], 1);
            d_det_score[b][pos] = ss[i];
            d_det_box[b][pos] = sbox[sslot[i]];
            d_det_label[b][pos] = c + 1;
        }
    }
}

// ---------------- kernel 3: per-image top-100 via radix select + tiny sort ----------------
__global__ void topk_kernel(float* __restrict__ out) {
    const int b = blockIdx.x;
    const int tid = threadIdx.x;     // 1024
    const int M = d_img_cnt[b];

    float* detOut = out + (size_t)b * DETS * 5;
    float* labOut = out + (size_t)Bn * DETS * 5 + (size_t)b * DETS;
    float* valOut = out + (size_t)Bn * DETS * 5 + (size_t)Bn * DETS + (size_t)b * DETS;

    __shared__ int hist[256];
    __shared__ unsigned s_prefix;
    __shared__ int s_rank;
    __shared__ int s_cnt;
    __shared__ unsigned long long keys[GCAP];
    __shared__ unsigned sbits[SCACHE];

    const bool cached = (M <= SCACHE);
    if (cached) {
        for (int i = tid; i < M; i += 1024)
            sbits[i] = __float_as_uint(d_det_score[b][i]);
        __syncthreads();
    }

    unsigned T = 0u;
    if (M >= DETS) {
        if (tid == 0) { s_prefix = 0u; s_rank = DETS; }
        __syncthreads();
        for (int shift = 24; shift >= 0; shift -= 8) {
            for (int i = tid; i < 256; i += 1024) hist[i] = 0;
            __syncthreads();
            const unsigned pfx = s_prefix;
            const unsigned hmask = (shift == 24) ? 0u : (0xffffffffu << (shift + 8));
            for (int i = tid; i < M; i += 1024) {
                const unsigned bits = cached ? sbits[i]
                                             : __float_as_uint(d_det_score[b][i]);
                if ((bits & hmask) == (pfx & hmask))
                    atomicAdd(&hist[(bits >> shift) & 255], 1);
            }
            __syncthreads();
            if (tid == 0) {
                int cum = 0, rank = s_rank, dsel = 0;
                for (int d = 255; d >= 0; d--) {
                    if (cum + hist[d] >= rank) { dsel = d; s_rank = rank - cum; break; }
                    cum += hist[d];
                }
                s_prefix |= (unsigned)dsel << shift;
            }
            __syncthreads();
        }
        T = s_prefix;
    }

    if (tid == 0) s_cnt = 0;
    __syncthreads();
    for (int i = tid; i < M; i += 1024) {
        const unsigned bits = cached ? sbits[i] : __float_as_uint(d_det_score[b][i]);
        if (bits >= T) {
            const int p = atomicAdd(&s_cnt, 1);
            if (p < GCAP)
                keys[p] = ((unsigned long long)bits << 32) |
                          (unsigned)(0x7fffffff - i);
        }
    }
    __syncthreads();
    const int cnt = (s_cnt < GCAP) ? s_cnt : GCAP;

    int P = 128;
    while (P < cnt) P <<= 1;
    for (int i = cnt + tid; i < P; i += 1024) keys[i] = 0ull;
    __syncthreads();

    for (int k = 2; k <= P; k <<= 1) {
        for (int j = k >> 1; j > 0; j >>= 1) {
            for (int i = tid; i < P; i += 1024) {
                const int ixj = i ^ j;
                if (ixj > i) {
                    const unsigned long long a = keys[i], c = keys[ixj];
                    const bool descBlock = ((i & k) == 0);
                    if (descBlock ? (a < c) : (a > c)) {
                        keys[i] = c; keys[ixj] = a;
                    }
                }
            }
            __syncthreads();
        }
    }

    if (tid < DETS) {
        const unsigned long long key = keys[tid];
        if (tid < cnt && key != 0ull) {
            const int idx = 0x7fffffff - (int)(unsigned)(key & 0xffffffffull);
            const float score = __uint_as_float((unsigned)(key >> 32));
            const float4 bx = d_det_box[b][idx];
            detOut[tid * 5 + 0] = bx.x;
            detOut[tid * 5 + 1] = bx.y;
            detOut[tid * 5 + 2] = bx.z;
            detOut[tid * 5 + 3] = bx.w;
            detOut[tid * 5 + 4] = score;
            labOut[tid] = (float)d_det_label[b][idx];
            valOut[tid] = 1.0f;
        } else {
            detOut[tid * 5 + 0] = 0.0f;
            detOut[tid * 5 + 1] = 0.0f;
            detOut[tid * 5 + 2] = 0.0f;
            detOut[tid * 5 + 3] = 0.0f;
            detOut[tid * 5 + 4] = 0.0f;
            labOut[tid] = 0.0f;
            valOut[tid] = 0.0f;
        }
    }
}

// ---------------- launch ----------------
extern "C" void kernel_launch(void* const* d_in, const int* in_sizes, int n_in,
                              void* d_out, int out_size) {
    const float* logits = nullptr;
    const float* boxreg = nullptr;
    const float* props  = nullptr;
    for (int i = 0; i < n_in; i++) {
        if (in_sizes[i] == Bn * Nn * Cn)          logits = (const float*)d_in[i];
        else if (in_sizes[i] == Bn * Nn * 4 * Cn) boxreg = (const float*)d_in[i];
        else if (in_sizes[i] == Bn * Nn * 4)      props = (const float*)d_in[i];
    }
    float* out = (float*)d_out;

    zero_counters_kernel<<<(Bn * NC + 255) / 256, 256>>>();
    softmax_gather_kernel<<<(Bn * Nn) / ROWS_PER_CTA, 32 * ROWS_PER_CTA>>>(logits, boxreg, props);
    nms_warp_kernel<<<(Bn * NC + 7) / 8, 256>>>();
    nms_mid_kernel<<<Bn * NC, NMSM_THREADS>>>();
    nms_big_kernel<<<Bn * NC, NMSB_THREADS>>>();
    topk_kernel<<<Bn, 1024>>>(out);
}

// round 14
// speedup vs baseline: 1.5981x; 1.1379x over previous
#include <cuda_runtime.h>
#include <math.h>

#define Bn 32
#define Nn 1000
#define Cn 105
#define NC 104            // classes 1..104
#define SCORE_TH 0.05f
#define NMS_TH 0.5f
#define DETS 100
#define IMG_W 1333.0f
#define IMG_H 800.0f
#define BBOX_CLIP 4.135166556742356f   // log(1000/16)
#define MAXCAND 1024                   // per (image,class) candidate cap; K <= 1000
#define GCAP 512                       // gather capacity for final small sort (pow2)
#define ROWS_PER_CTA 8                 // warps per CTA in softmax kernel
#define SCACHE 6144                    // shared score-bit cache in topk
#define AMB_BAND 1e-5f                 // threshold ambiguity band for fast-exp guard
#define KMASK 320                      // rank/mask NMS path limit
#define NWM 10                         // mask words per row (KMASK/32)
#define NMS_THREADS 256                // merged NMS kernel thread count

// ---------------- scratch (device globals; no allocation allowed) ----------------
__device__ float  d_cand_score[Bn][NC][Nn];
__device__ float4 d_cand_box[Bn][NC][Nn];
__device__ int    d_cand_n[Bn][NC][Nn];
__device__ int    d_cand_cnt[Bn * NC];

__device__ float  d_det_score[Bn][NC * Nn];
__device__ float4 d_det_box[Bn][NC * Nn];
__device__ int    d_det_label[Bn][NC * Nn];
__device__ int    d_img_cnt[Bn];

// ---------------- kernel 0: zero counters (graph-replay safe) ----------------
__global__ void zero_counters_kernel() {
    int i = blockIdx.x * blockDim.x + threadIdx.x;
    if (i < Bn * NC) d_cand_cnt[i] = 0;
    if (i < Bn) d_img_cnt[i] = 0;
}

// ---------------- kernel 1: warp-per-row softmax + threshold + decode ----------------
__global__ void softmax_gather_kernel(const float* __restrict__ logits,
                                      const float* __restrict__ boxreg,
                                      const float* __restrict__ props) {
    const int wid = threadIdx.x >> 5;
    const int lane = threadIdx.x & 31;
    const int row = blockIdx.x * ROWS_PER_CTA + wid;   // grid = B*N/8 = 4000
    const int b = row / Nn;
    const int n = row % Nn;

    const float* L = logits + (size_t)row * Cn;

    float l[4];
    #pragma unroll
    for (int q = 0; q < 4; q++) {
        const int j = lane + 32 * q;
        l[q] = (j < Cn) ? L[j] : -INFINITY;
    }

    float mx = fmaxf(fmaxf(l[0], l[1]), fmaxf(l[2], l[3]));
    #pragma unroll
    for (int o = 16; o > 0; o >>= 1) mx = fmaxf(mx, __shfl_xor_sync(0xffffffffu, mx, o));

    float eh[4];
    float s = 0.0f;
    #pragma unroll
    for (int q = 0; q < 4; q++) {
        const int j = lane + 32 * q;
        eh[q] = (j < Cn) ? __expf(l[q] - mx) : 0.0f;
        s += eh[q];
    }
    #pragma unroll
    for (int o = 16; o > 0; o >>= 1) s += __shfl_xor_sync(0xffffffffu, s, o);
    float inv_s = 1.0f / s;

    float ph[4];
    bool amb = false;
    #pragma unroll
    for (int q = 0; q < 4; q++) {
        const int j = lane + 32 * q;
        ph[q] = eh[q] * inv_s;
        if (j >= 1 && j < Cn && fabsf(ph[q] - SCORE_TH) < AMB_BAND) amb = true;
    }
    bool precise_row = false;
    if (__ballot_sync(0xffffffffu, amb)) {
        float sp = 0.0f;
        #pragma unroll
        for (int q = 0; q < 4; q++) {
            const int j = lane + 32 * q;
            eh[q] = (j < Cn) ? expf(l[q] - mx) : 0.0f;
            sp += eh[q];
        }
        #pragma unroll
        for (int o = 16; o > 0; o >>= 1) sp += __shfl_xor_sync(0xffffffffu, sp, o);
        inv_s = 1.0f / sp;
        #pragma unroll
        for (int q = 0; q < 4; q++) ph[q] = eh[q] * inv_s;
        precise_row = true;
    }

    const float4 pr = *(const float4*)(props + (size_t)row * 4);
    const float w  = pr.z - pr.x + 1.0f;
    const float h  = pr.w - pr.y + 1.0f;
    const float cx = pr.x + 0.5f * w;
    const float cy = pr.y + 0.5f * h;

    #pragma unroll
    for (int q = 0; q < 4; q++) {
        const int j = lane + 32 * q;
        if (j >= 1 && j < Cn && ph[q] > SCORE_TH) {
            const float p_store = precise_row ? ph[q] : expf(l[q] - mx) * inv_s;

            const float4 r = *(const float4*)(boxreg + ((size_t)row * Cn + j) * 4);
            const float dx = r.x / 10.0f;
            const float dy = r.y / 10.0f;
            const float dw = fminf(r.z / 5.0f, BBOX_CLIP);
            const float dh = fminf(r.w / 5.0f, BBOX_CLIP);
            const float pcx = dx * w + cx;
            const float pcy = dy * h + cy;
            const float pw = expf(dw) * w;
            const float ph2 = expf(dh) * h;
            float4 box;
            box.x = fminf(fmaxf(pcx - 0.5f * pw, 0.0f), IMG_W - 1.0f);
            box.y = fminf(fmaxf(pcy - 0.5f * ph2, 0.0f), IMG_H - 1.0f);
            box.z = fminf(fmaxf(pcx + 0.5f * pw - 1.0f, 0.0f), IMG_W - 1.0f);
            box.w = fminf(fmaxf(pcy + 0.5f * ph2 - 1.0f, 0.0f), IMG_H - 1.0f);

            const int c = j - 1;
            const int slot = atomicAdd(&d_cand_cnt[b * NC + c], 1);
            d_cand_score[b][c][slot] = p_store;
            d_cand_n[b][c][slot] = n;
            d_cand_box[b][c][slot] = box;
        }
    }
}

// ---------------- kernel 2: merged NMS (warp / mask / fallback paths) ----------------
struct SmemMid {
    unsigned long long skey[KMASK];
    float4 sbox[KMASK];       // slot order
    float4 sbox2[KMASK];      // rank order
    float  sarea[KMASK];      // rank order
    short  perm[KMASK];       // rank -> slot
    short  rnk[KMASK];        // slot -> rank
    unsigned mask[KMASK * NWM];
    unsigned suppw[NWM];
};
struct SmemBig {
    float  ss[MAXCAND];
    int    sn[MAXCAND];
    short  sslot[MAXCAND];
    float4 sbox[MAXCAND];
    unsigned char supp[MAXCAND];
};
union SmemU {
    SmemMid mid;
    SmemBig big;
};

__global__ void nms_kernel() {
    __shared__ SmemU u;

    const int bc = blockIdx.x;           // 0 .. B*NC-1
    const int K = d_cand_cnt[bc];
    if (K == 0) return;
    const int b = bc / NC;
    const int c = bc % NC;
    const int tid = threadIdx.x;         // NMS_THREADS = 256

    // ================= path A: K <= 32, warp 0 only, register/shuffle =================
    if (K <= 32) {
        if (tid >= 32) return;
        const int lane = tid;

        if (K == 1) {
            if (lane == 0) {
                const int pos = atomicAdd(&d_img_cnt[b], 1);
                d_det_score[b][pos] = d_cand_score[b][c][0];
                d_det_box[b][pos] = d_cand_box[b][c][0];
                d_det_label[b][pos] = c + 1;
            }
            return;
        }

        const bool act = lane < K;
        const float sc = act ? d_cand_score[b][c][lane] : -INFINITY;
        const int   nn = act ? d_cand_n[b][c][lane] : 0x7fffffff;
        float4 bx = make_float4(0.0f, 0.0f, 0.0f, 0.0f);
        if (act) bx = d_cand_box[b][c][lane];

        int rank = 0;
        #pragma unroll 8
        for (int l = 0; l < 32; l++) {
            const float osc = __shfl_sync(0xffffffffu, sc, l);
            const int   onn = __shfl_sync(0xffffffffu, nn, l);
            if (osc > sc || (osc == sc && onn < nn)) rank++;
        }

        const float area = (bx.z - bx.x + 1.0f) * (bx.w - bx.y + 1.0f);

        unsigned myrow = 0;
        #pragma unroll 8
        for (int l = 0; l < 32; l++) {
            const int   orank = __shfl_sync(0xffffffffu, rank, l);
            const float ox1 = __shfl_sync(0xffffffffu, bx.x, l);
            const float oy1 = __shfl_sync(0xffffffffu, bx.y, l);
            const float ox2 = __shfl_sync(0xffffffffu, bx.z, l);
            const float oy2 = __shfl_sync(0xffffffffu, bx.w, l);
            const float oarea = __shfl_sync(0xffffffffu, area, l);
            const bool oact = (orank < K);
            if (act && oact && orank > rank) {
                const float iw = fmaxf(fminf(ox2, bx.z) - fmaxf(ox1, bx.x) + 1.0f, 0.0f);
                const float ih = fmaxf(fminf(oy2, bx.w) - fmaxf(oy1, bx.y) + 1.0f, 0.0f);
                const float inter = iw * ih;
                const float iou = inter / (area + oarea - inter);
                if (iou > NMS_TH) myrow |= 1u << orank;
            }
        }
        unsigned rows[32];
        #pragma unroll 8
        for (int l = 0; l < 32; l++) {
            const int   orank = __shfl_sync(0xffffffffu, rank, l);
            const unsigned orow = __shfl_sync(0xffffffffu, myrow, l);
            if (orank < 32) rows[orank] = orow;
        }
        unsigned suppm = 0;
        for (int t = 0; t < K; t++) {
            if (!((suppm >> t) & 1u)) suppm |= rows[t];
        }

        const bool keep = act && !((suppm >> rank) & 1u);
        const unsigned km = __ballot_sync(0xffffffffu, keep);
        const int cnt = __popc(km);
        if (cnt == 0) return;
        const int leader = __ffs(km) - 1;
        int base = 0;
        if (lane == leader) base = atomicAdd(&d_img_cnt[b], cnt);
        base = __shfl_sync(0xffffffffu, base, leader);
        if (keep) {
            const int pos = base + __popc(km & ((1u << lane) - 1u));
            d_det_score[b][pos] = sc;
            d_det_box[b][pos] = bx;
            d_det_label[b][pos] = c + 1;
        }
        return;
    }

    // ================= path B: 32 < K <= KMASK, rank + mask, chunked scan =================
    if (K <= KMASK) {
        // load; key = (score_bits << 32) | (0x7fffffff - n)
        for (int i = tid; i < K; i += NMS_THREADS) {
            const unsigned sb = __float_as_uint(d_cand_score[b][c][i]);
            u.mid.skey[i] = ((unsigned long long)sb << 32) |
                            (unsigned)(0x7fffffff - d_cand_n[b][c][i]);
            u.mid.sbox[i] = d_cand_box[b][c][i];
        }
        __syncthreads();

        // rank by counting (keys unique); broadcast smem reads (j warp-uniform)
        for (int i = tid; i < K; i += NMS_THREADS) {
            const unsigned long long me = u.mid.skey[i];
            int r = 0;
            for (int j = 0; j < K; j++) r += (u.mid.skey[j] > me);
            u.mid.rnk[i] = (short)r;
            u.mid.perm[r] = (short)i;
        }
        __syncthreads();

        // stage boxes + areas in rank order
        for (int r = tid; r < K; r += NMS_THREADS) {
            const float4 A = u.mid.sbox[u.mid.perm[r]];
            u.mid.sbox2[r] = A;
            u.mid.sarea[r] = (A.z - A.x + 1.0f) * (A.w - A.y + 1.0f);
        }
        __syncthreads();

        const int nw = (K + 31) >> 5;
        // balanced mask build: one work item = one (row, word) pair
        const int totalWork = K * nw;
        for (int t = tid; t < totalWork; t += NMS_THREADS) {
            const int r = t / nw;
            const int w = t - r * nw;
            const int jbase = w << 5;
            const int jend = min(jbase + 32, K);
            unsigned m = 0;
            if (jend > r + 1) {
                const float4 A = u.mid.sbox2[r];
                const float areaA = u.mid.sarea[r];
                for (int j = max(jbase, r + 1); j < jend; j++) {
                    const float4 Bx = u.mid.sbox2[j];
                    const float iw = fmaxf(fminf(A.z, Bx.z) - fmaxf(A.x, Bx.x) + 1.0f, 0.0f);
                    const float ih = fmaxf(fminf(A.w, Bx.w) - fmaxf(A.y, Bx.y) + 1.0f, 0.0f);
                    const float inter = iw * ih;
                    const float iou = inter / (areaA + u.mid.sarea[j] - inter);
                    if (iou > NMS_TH) m |= 1u << (j & 31);
                }
            }
            u.mid.mask[r * NWM + w] = m;
        }
        __syncthreads();

        // chunked greedy scan by warp 0: one shuffle per 32 ranks instead of per rank.
        // All lanes redundantly run the in-chunk scan from the diagonal word (broadcast LDS).
        if (tid < 32) {
            unsigned sw = 0;   // lane w accumulates suppression word w from kept rows
            for (int cch = 0; cch < nw; cch++) {
                unsigned cur = __shfl_sync(0xffffffffu, sw, cch);   // carry-in for word cch
                const int iend = min(32, K - (cch << 5));
                unsigned keptbits = 0;
                #pragma unroll
                for (int t = 0; t < 32; t++) {
                    const unsigned rowword = u.mid.mask[((cch << 5) + t) * NWM + cch];
                    if (t < iend && !((cur >> t) & 1u)) {
                        cur |= rowword;
                        keptbits |= 1u << t;
                    }
                }
                if (tid == cch) sw = cur;
                else if (tid > cch && tid < nw) {
                    unsigned kb = keptbits;
                    while (kb) {
                        const int t = __ffs(kb) - 1;
                        kb &= kb - 1;
                        sw |= u.mid.mask[((cch << 5) + t) * NWM + tid];
                    }
                }
            }
            if (tid < nw) u.mid.suppw[tid] = sw;
        }
        __syncthreads();

        for (int i = tid; i < K; i += NMS_THREADS) {
            const int r = u.mid.rnk[i];
            if (!((u.mid.suppw[r >> 5] >> (r & 31)) & 1u)) {
                const int pos = atomicAdd(&d_img_cnt[b], 1);
                d_det_score[b][pos] = __uint_as_float((unsigned)(u.mid.skey[i] >> 32));
                d_det_box[b][pos] = u.mid.sbox[i];
                d_det_label[b][pos] = c + 1;
            }
        }
        return;
    }

    // ================= path C: K > KMASK fallback (sort + greedy) =================
    int P = 1;
    while (P < K) P <<= 1;

    for (int i = tid; i < P; i += NMS_THREADS) {
        if (i < K) {
            u.big.ss[i] = d_cand_score[b][c][i];
            u.big.sn[i] = d_cand_n[b][c][i];
            u.big.sbox[i] = d_cand_box[b][c][i];
        } else {
            u.big.ss[i] = -INFINITY;
            u.big.sn[i] = 0x7fffffff;
        }
        u.big.sslot[i] = (short)i;
        u.big.supp[i] = (i >= K);
    }
    __syncthreads();

    for (int k = 2; k <= P; k <<= 1) {
        for (int j = k >> 1; j > 0; j >>= 1) {
            for (int i = tid; i < P; i += NMS_THREADS) {
                const int ixj = i ^ j;
                if (ixj > i) {
                    const float a = u.big.ss[i], bb = u.big.ss[ixj];
                    const int   na = u.big.sn[i], nb = u.big.sn[ixj];
                    const bool i_after = (a < bb) || (a == bb && na > nb);
                    const bool dirAsc = ((i & k) == 0);
                    if (i_after == dirAsc) {
                        u.big.ss[i] = bb;  u.big.ss[ixj] = a;
                        u.big.sn[i] = nb;  u.big.sn[ixj] = na;
                        const short t = u.big.sslot[i];
                        u.big.sslot[i] = u.big.sslot[ixj];
                        u.big.sslot[ixj] = t;
                    }
                }
            }
            __syncthreads();
        }
    }

    for (int i = 0; i < K; i++) {
        __syncthreads();
        if (u.big.supp[i]) continue;
        const float4 A = u.big.sbox[u.big.sslot[i]];
        const float areaA = (A.z - A.x + 1.0f) * (A.w - A.y + 1.0f);
        for (int j = i + 1 + tid; j < K; j += NMS_THREADS) {
            if (u.big.supp[j]) continue;
            const float4 Bx = u.big.sbox[u.big.sslot[j]];
            const float iw = fmaxf(fminf(A.z, Bx.z) - fmaxf(A.x, Bx.x) + 1.0f, 0.0f);
            const float ih = fmaxf(fminf(A.w, Bx.w) - fmaxf(A.y, Bx.y) + 1.0f, 0.0f);
            const float inter = iw * ih;
            const float areaB = (Bx.z - Bx.x + 1.0f) * (Bx.w - Bx.y + 1.0f);
            const float iou = inter / (areaA + areaB - inter);
            if (iou > NMS_TH) u.big.supp[j] = 1;
        }
    }
    __syncthreads();
    for (int i = tid; i < K; i += NMS_THREADS) {
        if (!u.big.supp[i]) {
            const int pos = atomicAdd(&d_img_cnt[b], 1);
            d_det_score[b][pos] = u.big.ss[i];
            d_det_box[b][pos] = u.big.sbox[u.big.sslot[i]];
            d_det_label[b][pos] = c + 1;
        }
    }
}

// ---------------- kernel 3: per-image top-100 via radix select + tiny sort ----------------
__global__ void topk_kernel(float* __restrict__ out) {
    const int b = blockIdx.x;
    const int tid = threadIdx.x;     // 1024
    const int M = d_img_cnt[b];

    float* detOut = out + (size_t)b * DETS * 5;
    float* labOut = out + (size_t)Bn * DETS * 5 + (size_t)b * DETS;
    float* valOut = out + (size_t)Bn * DETS * 5 + (size_t)Bn * DETS + (size_t)b * DETS;

    __shared__ int hist[256];
    __shared__ unsigned s_prefix;
    __shared__ int s_rank;
    __shared__ int s_cnt;
    __shared__ unsigned long long keys[GCAP];
    __shared__ unsigned sbits[SCACHE];

    const bool cached = (M <= SCACHE);
    if (cached) {
        for (int i = tid; i < M; i += 1024)
            sbits[i] = __float_as_uint(d_det_score[b][i]);
        __syncthreads();
    }

    unsigned T = 0u;
    if (M >= DETS) {
        if (tid == 0) { s_prefix = 0u; s_rank = DETS; }
        __syncthreads();
        for (int shift = 24; shift >= 0; shift -= 8) {
            for (int i = tid; i < 256; i += 1024) hist[i] = 0;
            __syncthreads();
            const unsigned pfx = s_prefix;
            const unsigned hmask = (shift == 24) ? 0u : (0xffffffffu << (shift + 8));
            for (int i = tid; i < M; i += 1024) {
                const unsigned bits = cached ? sbits[i]
                                             : __float_as_uint(d_det_score[b][i]);
                if ((bits & hmask) == (pfx & hmask))
                    atomicAdd(&hist[(bits >> shift) & 255], 1);
            }
            __syncthreads();
            if (tid == 0) {
                int cum = 0, rank = s_rank, dsel = 0;
                for (int d = 255; d >= 0; d--) {
                    if (cum + hist[d] >= rank) { dsel = d; s_rank = rank - cum; break; }
                    cum += hist[d];
                }
                s_prefix |= (unsigned)dsel << shift;
            }
            __syncthreads();
        }
        T = s_prefix;
    }

    if (tid == 0) s_cnt = 0;
    __syncthreads();
    for (int i = tid; i < M; i += 1024) {
        const unsigned bits = cached ? sbits[i] : __float_as_uint(d_det_score[b][i]);
        if (bits >= T) {
            const int p = atomicAdd(&s_cnt, 1);
            if (p < GCAP)
                keys[p] = ((unsigned long long)bits << 32) |
                          (unsigned)(0x7fffffff - i);
        }
    }
    __syncthreads();
    const int cnt = (s_cnt < GCAP) ? s_cnt : GCAP;

    int P = 128;
    while (P < cnt) P <<= 1;
    for (int i = cnt + tid; i < P; i += 1024) keys[i] = 0ull;
    __syncthreads();

    for (int k = 2; k <= P; k <<= 1) {
        for (int j = k >> 1; j > 0; j >>= 1) {
            for (int i = tid; i < P; i += 1024) {
                const int ixj = i ^ j;
                if (ixj > i) {
                    const unsigned long long a = keys[i], c = keys[ixj];
                    const bool descBlock = ((i & k) == 0);
                    if (descBlock ? (a < c) : (a > c)) {
                        keys[i] = c; keys[ixj] = a;
                    }
                }
            }
            __syncthreads();
        }
    }

    if (tid < DETS) {
        const unsigned long long key = keys[tid];
        if (tid < cnt && key != 0ull) {
            const int idx = 0x7fffffff - (int)(unsigned)(key & 0xffffffffull);
            const float score = __uint_as_float((unsigned)(key >> 32));
            const float4 bx = d_det_box[b][idx];
            detOut[tid * 5 + 0] = bx.x;
            detOut[tid * 5 + 1] = bx.y;
            detOut[tid * 5 + 2] = bx.z;
            detOut[tid * 5 + 3] = bx.w;
            detOut[tid * 5 + 4] = score;
            labOut[tid] = (float)d_det_label[b][idx];
            valOut[tid] = 1.0f;
        } else {
            detOut[tid * 5 + 0] = 0.0f;
            detOut[tid * 5 + 1] = 0.0f;
            detOut[tid * 5 + 2] = 0.0f;
            detOut[tid * 5 + 3] = 0.0f;
            detOut[tid * 5 + 4] = 0.0f;
            labOut[tid] = 0.0f;
            valOut[tid] = 0.0f;
        }
    }
}

// ---------------- launch ----------------
extern "C" void kernel_launch(void* const* d_in, const int* in_sizes, int n_in,
                              void* d_out, int out_size) {
    const float* logits = nullptr;
    const float* boxreg = nullptr;
    const float* props  = nullptr;
    for (int i = 0; i < n_in; i++) {
        if (in_sizes[i] == Bn * Nn * Cn)          logits = (const float*)d_in[i];
        else if (in_sizes[i] == Bn * Nn * 4 * Cn) boxreg = (const float*)d_in[i];
        else if (in_sizes[i] == Bn * Nn * 4)      props = (const float*)d_in[i];
    }
    float* out = (float*)d_out;

    zero_counters_kernel<<<(Bn * NC + 255) / 256, 256>>>();
    softmax_gather_kernel<<<(Bn * Nn) / ROWS_PER_CTA, 32 * ROWS_PER_CTA>>>(logits, boxreg, props);
    nms_kernel<<<Bn * NC, NMS_THREADS>>>();
    topk_kernel<<<Bn, 1024>>>(out);
}

// round 16
// speedup vs baseline: 1.8845x; 1.1792x over previous
#include <cuda_runtime.h>
#include <math.h>

#define Bn 32
#define Nn 1000
#define Cn 105
#define NC 104            // classes 1..104
#define SCORE_TH 0.05f
#define NMS_TH 0.5f
#define DETS 100
#define IMG_W 1333.0f
#define IMG_H 800.0f
#define BBOX_CLIP 4.135166556742356f   // log(1000/16)
#define MAXCAND 1024                   // per (image,class) candidate cap; K <= 1000
#define GCAP 512                       // gather capacity for final small sort (pow2)
#define ROWS_PER_CTA 8                 // warps per CTA in softmax kernel
#define AMB_BAND 1e-5f                 // threshold ambiguity band for fast-exp guard
#define KMASK 320                      // rank/mask NMS path limit
#define NWM 10                         // mask words per row (KMASK/32)
#define NMS_THREADS 256                // merged NMS kernel thread count
#define TOPK_THREADS 512               // topk kernel thread count

// ---------------- scratch (device globals; no allocation allowed) ----------------
__device__ float  d_cand_score[Bn][NC][Nn];
__device__ float4 d_cand_box[Bn][NC][Nn];
__device__ int    d_cand_n[Bn][NC][Nn];
__device__ int    d_cand_cnt[Bn * NC];

__device__ float  d_det_score[Bn][NC * Nn];
__device__ float4 d_det_box[Bn][NC * Nn];
__device__ int    d_det_label[Bn][NC * Nn];
__device__ int    d_img_cnt[Bn];

// ---------------- kernel 0: zero counters (graph-replay safe) ----------------
__global__ void zero_counters_kernel() {
    int i = blockIdx.x * blockDim.x + threadIdx.x;
    if (i < Bn * NC) d_cand_cnt[i] = 0;
    if (i < Bn) d_img_cnt[i] = 0;
}

// ---------------- kernel 1: warp-per-row softmax + threshold + decode ----------------
__global__ void softmax_gather_kernel(const float* __restrict__ logits,
                                      const float* __restrict__ boxreg,
                                      const float* __restrict__ props) {
    const int wid = threadIdx.x >> 5;
    const int lane = threadIdx.x & 31;
    const int row = blockIdx.x * ROWS_PER_CTA + wid;   // grid = B*N/8 = 4000
    const int b = row / Nn;
    const int n = row % Nn;

    const float* L = logits + (size_t)row * Cn;

    float l[4];
    #pragma unroll
    for (int q = 0; q < 4; q++) {
        const int j = lane + 32 * q;
        l[q] = (j < Cn) ? L[j] : -INFINITY;
    }

    float mx = fmaxf(fmaxf(l[0], l[1]), fmaxf(l[2], l[3]));
    #pragma unroll
    for (int o = 16; o > 0; o >>= 1) mx = fmaxf(mx, __shfl_xor_sync(0xffffffffu, mx, o));

    float eh[4];
    float s = 0.0f;
    #pragma unroll
    for (int q = 0; q < 4; q++) {
        const int j = lane + 32 * q;
        eh[q] = (j < Cn) ? __expf(l[q] - mx) : 0.0f;
        s += eh[q];
    }
    #pragma unroll
    for (int o = 16; o > 0; o >>= 1) s += __shfl_xor_sync(0xffffffffu, s, o);
    float inv_s = 1.0f / s;

    float ph[4];
    bool amb = false;
    #pragma unroll
    for (int q = 0; q < 4; q++) {
        const int j = lane + 32 * q;
        ph[q] = eh[q] * inv_s;
        if (j >= 1 && j < Cn && fabsf(ph[q] - SCORE_TH) < AMB_BAND) amb = true;
    }
    bool precise_row = false;
    if (__ballot_sync(0xffffffffu, amb)) {
        float sp = 0.0f;
        #pragma unroll
        for (int q = 0; q < 4; q++) {
            const int j = lane + 32 * q;
            eh[q] = (j < Cn) ? expf(l[q] - mx) : 0.0f;
            sp += eh[q];
        }
        #pragma unroll
        for (int o = 16; o > 0; o >>= 1) sp += __shfl_xor_sync(0xffffffffu, sp, o);
        inv_s = 1.0f / sp;
        #pragma unroll
        for (int q = 0; q < 4; q++) ph[q] = eh[q] * inv_s;
        precise_row = true;
    }

    const float4 pr = *(const float4*)(props + (size_t)row * 4);
    const float w  = pr.z - pr.x + 1.0f;
    const float h  = pr.w - pr.y + 1.0f;
    const float cx = pr.x + 0.5f * w;
    const float cy = pr.y + 0.5f * h;

    #pragma unroll
    for (int q = 0; q < 4; q++) {
        const int j = lane + 32 * q;
        if (j >= 1 && j < Cn && ph[q] > SCORE_TH) {
            const float p_store = precise_row ? ph[q] : expf(l[q] - mx) * inv_s;

            const float4 r = *(const float4*)(boxreg + ((size_t)row * Cn + j) * 4);
            const float dx = r.x / 10.0f;
            const float dy = r.y / 10.0f;
            const float dw = fminf(r.z / 5.0f, BBOX_CLIP);
            const float dh = fminf(r.w / 5.0f, BBOX_CLIP);
            const float pcx = dx * w + cx;
            const float pcy = dy * h + cy;
            const float pw = expf(dw) * w;
            const float ph2 = expf(dh) * h;
            float4 box;
            box.x = fminf(fmaxf(pcx - 0.5f * pw, 0.0f), IMG_W - 1.0f);
            box.y = fminf(fmaxf(pcy - 0.5f * ph2, 0.0f), IMG_H - 1.0f);
            box.z = fminf(fmaxf(pcx + 0.5f * pw - 1.0f, 0.0f), IMG_W - 1.0f);
            box.w = fminf(fmaxf(pcy + 0.5f * ph2 - 1.0f, 0.0f), IMG_H - 1.0f);

            const int c = j - 1;
            const int slot = atomicAdd(&d_cand_cnt[b * NC + c], 1);
            d_cand_score[b][c][slot] = p_store;
            d_cand_n[b][c][slot] = n;
            d_cand_box[b][c][slot] = box;
        }
    }
}

// ---------------- kernel 2: merged NMS (warp / mask / fallback paths) ----------------
struct SmemMid {
    unsigned long long skey[KMASK];
    float4 sbox[KMASK];       // slot order
    float4 sbox2[KMASK];      // rank order
    float  sarea[KMASK];      // rank order
    short  perm[KMASK];       // rank -> slot
    short  rnk[KMASK];        // slot -> rank
    unsigned mask[KMASK * NWM];
    unsigned suppw[NWM];
};
struct SmemBig {
    float  ss[MAXCAND];
    int    sn[MAXCAND];
    short  sslot[MAXCAND];
    float4 sbox[MAXCAND];
    unsigned char supp[MAXCAND];
};
union SmemU {
    SmemMid mid;
    SmemBig big;
};

__global__ void nms_kernel() {
    __shared__ SmemU u;

    const int bc = blockIdx.x;           // 0 .. B*NC-1
    const int K = d_cand_cnt[bc];
    if (K == 0) return;
    const int b = bc / NC;
    const int c = bc % NC;
    const int tid = threadIdx.x;         // NMS_THREADS = 256

    // ================= path A: K <= 32, warp 0 only, register/shuffle =================
    if (K <= 32) {
        if (tid >= 32) return;
        const int lane = tid;

        if (K == 1) {
            if (lane == 0) {
                const int pos = atomicAdd(&d_img_cnt[b], 1);
                d_det_score[b][pos] = d_cand_score[b][c][0];
                d_det_box[b][pos] = d_cand_box[b][c][0];
                d_det_label[b][pos] = c + 1;
            }
            return;
        }

        const bool act = lane < K;
        const float sc = act ? d_cand_score[b][c][lane] : -INFINITY;
        const int   nn = act ? d_cand_n[b][c][lane] : 0x7fffffff;
        float4 bx = make_float4(0.0f, 0.0f, 0.0f, 0.0f);
        if (act) bx = d_cand_box[b][c][lane];

        int rank = 0;
        #pragma unroll 8
        for (int l = 0; l < 32; l++) {
            const float osc = __shfl_sync(0xffffffffu, sc, l);
            const int   onn = __shfl_sync(0xffffffffu, nn, l);
            if (osc > sc || (osc == sc && onn < nn)) rank++;
        }

        const float area = (bx.z - bx.x + 1.0f) * (bx.w - bx.y + 1.0f);

        unsigned myrow = 0;
        #pragma unroll 8
        for (int l = 0; l < 32; l++) {
            const int   orank = __shfl_sync(0xffffffffu, rank, l);
            const float ox1 = __shfl_sync(0xffffffffu, bx.x, l);
            const float oy1 = __shfl_sync(0xffffffffu, bx.y, l);
            const float ox2 = __shfl_sync(0xffffffffu, bx.z, l);
            const float oy2 = __shfl_sync(0xffffffffu, bx.w, l);
            const float oarea = __shfl_sync(0xffffffffu, area, l);
            const bool oact = (orank < K);
            if (act && oact && orank > rank) {
                const float iw = fmaxf(fminf(ox2, bx.z) - fmaxf(ox1, bx.x) + 1.0f, 0.0f);
                const float ih = fmaxf(fminf(oy2, bx.w) - fmaxf(oy1, bx.y) + 1.0f, 0.0f);
                const float inter = iw * ih;
                const float iou = inter / (area + oarea - inter);
                if (iou > NMS_TH) myrow |= 1u << orank;
            }
        }
        unsigned rows[32];
        #pragma unroll 8
        for (int l = 0; l < 32; l++) {
            const int   orank = __shfl_sync(0xffffffffu, rank, l);
            const unsigned orow = __shfl_sync(0xffffffffu, myrow, l);
            if (orank < 32) rows[orank] = orow;
        }
        unsigned suppm = 0;
        for (int t = 0; t < K; t++) {
            if (!((suppm >> t) & 1u)) suppm |= rows[t];
        }

        const bool keep = act && !((suppm >> rank) & 1u);
        const unsigned km = __ballot_sync(0xffffffffu, keep);
        const int cnt = __popc(km);
        if (cnt == 0) return;
        const int leader = __ffs(km) - 1;
        int base = 0;
        if (lane == leader) base = atomicAdd(&d_img_cnt[b], cnt);
        base = __shfl_sync(0xffffffffu, base, leader);
        if (keep) {
            const int pos = base + __popc(km & ((1u << lane) - 1u));
            d_det_score[b][pos] = sc;
            d_det_box[b][pos] = bx;
            d_det_label[b][pos] = c + 1;
        }
        return;
    }

    // ================= path B: 32 < K <= KMASK, rank + mask, chunked scan =================
    if (K <= KMASK) {
        for (int i = tid; i < K; i += NMS_THREADS) {
            const unsigned sb = __float_as_uint(d_cand_score[b][c][i]);
            u.mid.skey[i] = ((unsigned long long)sb << 32) |
                            (unsigned)(0x7fffffff - d_cand_n[b][c][i]);
            u.mid.sbox[i] = d_cand_box[b][c][i];
        }
        __syncthreads();

        for (int i = tid; i < K; i += NMS_THREADS) {
            const unsigned long long me = u.mid.skey[i];
            int r = 0;
            for (int j = 0; j < K; j++) r += (u.mid.skey[j] > me);
            u.mid.rnk[i] = (short)r;
            u.mid.perm[r] = (short)i;
        }
        __syncthreads();

        for (int r = tid; r < K; r += NMS_THREADS) {
            const float4 A = u.mid.sbox[u.mid.perm[r]];
            u.mid.sbox2[r] = A;
            u.mid.sarea[r] = (A.z - A.x + 1.0f) * (A.w - A.y + 1.0f);
        }
        __syncthreads();

        const int nw = (K + 31) >> 5;
        const int totalWork = K * nw;
        for (int t = tid; t < totalWork; t += NMS_THREADS) {
            const int r = t / nw;
            const int w = t - r * nw;
            const int jbase = w << 5;
            const int jend = min(jbase + 32, K);
            unsigned m = 0;
            if (jend > r + 1) {
                const float4 A = u.mid.sbox2[r];
                const float areaA = u.mid.sarea[r];
                for (int j = max(jbase, r + 1); j < jend; j++) {
                    const float4 Bx = u.mid.sbox2[j];
                    const float iw = fmaxf(fminf(A.z, Bx.z) - fmaxf(A.x, Bx.x) + 1.0f, 0.0f);
                    const float ih = fmaxf(fminf(A.w, Bx.w) - fmaxf(A.y, Bx.y) + 1.0f, 0.0f);
                    const float inter = iw * ih;
                    const float iou = inter / (areaA + u.mid.sarea[j] - inter);
                    if (iou > NMS_TH) m |= 1u << (j & 31);
                }
            }
            u.mid.mask[r * NWM + w] = m;
        }
        __syncthreads();

        // chunked greedy scan by warp 0: one shuffle per 32 ranks
        if (tid < 32) {
            unsigned sw = 0;
            for (int cch = 0; cch < nw; cch++) {
                unsigned cur = __shfl_sync(0xffffffffu, sw, cch);
                const int iend = min(32, K - (cch << 5));
                unsigned keptbits = 0;
                #pragma unroll
                for (int t = 0; t < 32; t++) {
                    const unsigned rowword = u.mid.mask[((cch << 5) + t) * NWM + cch];
                    if (t < iend && !((cur >> t) & 1u)) {
                        cur |= rowword;
                        keptbits |= 1u << t;
                    }
                }
                if (tid == cch) sw = cur;
                else if (tid > cch && tid < nw) {
                    unsigned kb = keptbits;
                    while (kb) {
                        const int t = __ffs(kb) - 1;
                        kb &= kb - 1;
                        sw |= u.mid.mask[((cch << 5) + t) * NWM + tid];
                    }
                }
            }
            if (tid < nw) u.mid.suppw[tid] = sw;
        }
        __syncthreads();

        for (int i = tid; i < K; i += NMS_THREADS) {
            const int r = u.mid.rnk[i];
            if (!((u.mid.suppw[r >> 5] >> (r & 31)) & 1u)) {
                const int pos = atomicAdd(&d_img_cnt[b], 1);
                d_det_score[b][pos] = __uint_as_float((unsigned)(u.mid.skey[i] >> 32));
                d_det_box[b][pos] = u.mid.sbox[i];
                d_det_label[b][pos] = c + 1;
            }
        }
        return;
    }

    // ================= path C: K > KMASK fallback (sort + greedy) =================
    int P = 1;
    while (P < K) P <<= 1;

    for (int i = tid; i < P; i += NMS_THREADS) {
        if (i < K) {
            u.big.ss[i] = d_cand_score[b][c][i];
            u.big.sn[i] = d_cand_n[b][c][i];
            u.big.sbox[i] = d_cand_box[b][c][i];
        } else {
            u.big.ss[i] = -INFINITY;
            u.big.sn[i] = 0x7fffffff;
        }
        u.big.sslot[i] = (short)i;
        u.big.supp[i] = (i >= K);
    }
    __syncthreads();

    for (int k = 2; k <= P; k <<= 1) {
        for (int j = k >> 1; j > 0; j >>= 1) {
            for (int i = tid; i < P; i += NMS_THREADS) {
                const int ixj = i ^ j;
                if (ixj > i) {
                    const float a = u.big.ss[i], bb = u.big.ss[ixj];
                    const int   na = u.big.sn[i], nb = u.big.sn[ixj];
                    const bool i_after = (a < bb) || (a == bb && na > nb);
                    const bool dirAsc = ((i & k) == 0);
                    if (i_after == dirAsc) {
                        u.big.ss[i] = bb;  u.big.ss[ixj] = a;
                        u.big.sn[i] = nb;  u.big.sn[ixj] = na;
                        const short t = u.big.sslot[i];
                        u.big.sslot[i] = u.big.sslot[ixj];
                        u.big.sslot[ixj] = t;
                    }
                }
            }
            __syncthreads();
        }
    }

    for (int i = 0; i < K; i++) {
        __syncthreads();
        if (u.big.supp[i]) continue;
        const float4 A = u.big.sbox[u.big.sslot[i]];
        const float areaA = (A.z - A.x + 1.0f) * (A.w - A.y + 1.0f);
        for (int j = i + 1 + tid; j < K; j += NMS_THREADS) {
            if (u.big.supp[j]) continue;
            const float4 Bx = u.big.sbox[u.big.sslot[j]];
            const float iw = fmaxf(fminf(A.z, Bx.z) - fmaxf(A.x, Bx.x) + 1.0f, 0.0f);
            const float ih = fmaxf(fminf(A.w, Bx.w) - fmaxf(A.y, Bx.y) + 1.0f, 0.0f);
            const float inter = iw * ih;
            const float areaB = (Bx.z - Bx.x + 1.0f) * (Bx.w - Bx.y + 1.0f);
            const float iou = inter / (areaA + areaB - inter);
            if (iou > NMS_TH) u.big.supp[j] = 1;
        }
    }
    __syncthreads();
    for (int i = tid; i < K; i += NMS_THREADS) {
        if (!u.big.supp[i]) {
            const int pos = atomicAdd(&d_img_cnt[b], 1);
            d_det_score[b][pos] = u.big.ss[i];
            d_det_box[b][pos] = u.big.sbox[u.big.sslot[i]];
            d_det_label[b][pos] = c + 1;
        }
    }
}

// ---------------- kernel 3: per-image top-100 via radix select (parallel digit pick) ----------------
__global__ void topk_kernel(float* __restrict__ out) {
    const int b = blockIdx.x;
    const int tid = threadIdx.x;     // TOPK_THREADS = 512
    const int M = d_img_cnt[b];

    float* detOut = out + (size_t)b * DETS * 5;
    float* labOut = out + (size_t)Bn * DETS * 5 + (size_t)b * DETS;
    float* valOut = out + (size_t)Bn * DETS * 5 + (size_t)Bn * DETS + (size_t)b * DETS;

    __shared__ int hist[256];
    __shared__ int wsum[8];          // per-warp scan totals
    __shared__ unsigned s_prefix;
    __shared__ int s_rank;
    __shared__ int s_cnt;
    __shared__ unsigned long long keys[GCAP];

    // -------- phase 1: radix select bit-pattern T of the DETS-th largest score --------
    unsigned T = 0u;                 // if M < DETS: keep everything
    if (M >= DETS) {
        if (tid == 0) { s_prefix = 0u; s_rank = DETS; }
        __syncthreads();
        for (int shift = 24; shift >= 0; shift -= 8) {
            if (tid < 256) hist[tid] = 0;
            __syncthreads();
            const unsigned pfx = s_prefix;
            const int rank = s_rank;
            const unsigned hmask = (shift == 24) ? 0u : (0xffffffffu << (shift + 8));
            for (int i = tid; i < M; i += TOPK_THREADS) {
                const unsigned bits = __float_as_uint(d_det_score[b][i]);
                if ((bits & hmask) == (pfx & hmask))
                    atomicAdd(&hist[(bits >> shift) & 255], 1);
            }
            __syncthreads();

            // parallel digit selection: thread tid<256 owns bin d = 255 - tid.
            // suffix_sum(d) over bins >= d == inclusive prefix over reversed order.
            if (tid < 256) {
                const int d = 255 - tid;
                const int v = hist[d];
                const int lane = tid & 31;
                const int wrp = tid >> 5;
                int incl = v;
                #pragma unroll
                for (int o = 1; o < 32; o <<= 1) {
                    const int other = __shfl_up_sync(0xffffffffu, incl, o);
                    if (lane >= o) incl += other;
                }
                if (lane == 31) wsum[wrp] = incl;
                __syncwarp();
                // (block-level combine needs all 8 warp totals)
            }
            __syncthreads();
            if (tid < 256) {
                const int d = 255 - tid;
                const int v = hist[d];
                const int lane = tid & 31;
                const int wrp = tid >> 5;
                int incl = v;
                #pragma unroll
                for (int o = 1; o < 32; o <<= 1) {
                    const int other = __shfl_up_sync(0xffffffffu, incl, o);
                    if (lane >= o) incl += other;
                }
                int off = 0;
                #pragma unroll
                for (int wq = 0; wq < 8; wq++) if (wq < wrp) off += wsum[wq];
                incl += off;
                const int excl = incl - v;
                if (excl < rank && rank <= incl) {   // exactly one thread (v > 0 here)
                    s_prefix = pfx | ((unsigned)d << shift);
                    s_rank = rank - excl;
                }
            }
            __syncthreads();
        }
        T = s_prefix;
    }

    // -------- phase 2: gather all elements with bits >= T --------
    if (tid == 0) s_cnt = 0;
    __syncthreads();
    for (int i = tid; i < M; i += TOPK_THREADS) {
        const unsigned bits = __float_as_uint(d_det_score[b][i]);
        if (bits >= T) {
            const int p = atomicAdd(&s_cnt, 1);
            if (p < GCAP)
                keys[p] = ((unsigned long long)bits << 32) |
                          (unsigned)(0x7fffffff - i);
        }
    }
    __syncthreads();
    const int cnt = (s_cnt < GCAP) ? s_cnt : GCAP;

    int P = 128;
    while (P < cnt) P <<= 1;
    for (int i = cnt + tid; i < P; i += TOPK_THREADS) keys[i] = 0ull;
    __syncthreads();

    // -------- phase 3: bitonic sort (descending) --------
    for (int k = 2; k <= P; k <<= 1) {
        for (int j = k >> 1; j > 0; j >>= 1) {
            for (int i = tid; i < P; i += TOPK_THREADS) {
                const int ixj = i ^ j;
                if (ixj > i) {
                    const unsigned long long a = keys[i], c = keys[ixj];
                    const bool descBlock = ((i & k) == 0);
                    if (descBlock ? (a < c) : (a > c)) {
                        keys[i] = c; keys[ixj] = a;
                    }
                }
            }
            __syncthreads();
        }
    }

    // -------- phase 4: parallel output write --------
    if (tid < DETS) {
        const unsigned long long key = keys[tid];
        if (tid < cnt && key != 0ull) {
            const int idx = 0x7fffffff - (int)(unsigned)(key & 0xffffffffull);
            const float score = __uint_as_float((unsigned)(key >> 32));
            const float4 bx = d_det_box[b][idx];
            detOut[tid * 5 + 0] = bx.x;
            detOut[tid * 5 + 1] = bx.y;
            detOut[tid * 5 + 2] = bx.z;
            detOut[tid * 5 + 3] = bx.w;
            detOut[tid * 5 + 4] = score;
            labOut[tid] = (float)d_det_label[b][idx];
            valOut[tid] = 1.0f;
        } else {
            detOut[tid * 5 + 0] = 0.0f;
            detOut[tid * 5 + 1] = 0.0f;
            detOut[tid * 5 + 2] = 0.0f;
            detOut[tid * 5 + 3] = 0.0f;
            detOut[tid * 5 + 4] = 0.0f;
            labOut[tid] = 0.0f;
            valOut[tid] = 0.0f;
        }
    }
}

// ---------------- launch ----------------
extern "C" void kernel_launch(void* const* d_in, const int* in_sizes, int n_in,
                              void* d_out, int out_size) {
    const float* logits = nullptr;
    const float* boxreg = nullptr;
    const float* props  = nullptr;
    for (int i = 0; i < n_in; i++) {
        if (in_sizes[i] == Bn * Nn * Cn)          logits = (const float*)d_in[i];
        else if (in_sizes[i] == Bn * Nn * 4 * Cn) boxreg = (const float*)d_in[i];
        else if (in_sizes[i] == Bn * Nn * 4)      props = (const float*)d_in[i];
    }
    float* out = (float*)d_out;

    zero_counters_kernel<<<(Bn * NC + 255) / 256, 256>>>();
    softmax_gather_kernel<<<(Bn * Nn) / ROWS_PER_CTA, 32 * ROWS_PER_CTA>>>(logits, boxreg, props);
    nms_kernel<<<Bn * NC, NMS_THREADS>>>();
    topk_kernel<<<Bn, TOPK_THREADS>>>(out);
}

// round 17
// speedup vs baseline: 1.9580x; 1.0390x over previous
#include <cuda_runtime.h>
#include <math.h>

#define Bn 32
#define Nn 1000
#define Cn 105
#define NC 104            // classes 1..104
#define SCORE_TH 0.05f
#define NMS_TH 0.5f
#define DETS 100
#define IMG_W 1333.0f
#define IMG_H 800.0f
#define BBOX_CLIP 4.135166556742356f   // log(1000/16)
#define MAXCAND 1024                   // per (image,class) candidate cap; K <= 1000
#define GCAP 512                       // gather capacity (keys >= T)
#define ROWS_PER_CTA 8                 // warps per CTA in softmax kernel
#define AMB_BAND 1e-5f                 // threshold ambiguity band for fast-exp guard
#define KMASK 320                      // rank/mask NMS path limit
#define NWM 10                         // mask words per row (KMASK/32)
#define NMS_THREADS 256                // merged NMS kernel thread count
#define TOPK_THREADS 512               // topk kernel thread count

// ---------------- scratch (device globals; no allocation allowed) ----------------
__device__ float  d_cand_score[Bn][NC][Nn];
__device__ float4 d_cand_box[Bn][NC][Nn];
__device__ int    d_cand_n[Bn][NC][Nn];
__device__ int    d_cand_cnt[Bn * NC];

__device__ float  d_det_score[Bn][NC * Nn];
__device__ float4 d_det_box[Bn][NC * Nn];
__device__ int    d_det_label[Bn][NC * Nn];
__device__ int    d_img_cnt[Bn];

// ---------------- kernel 0: zero counters (graph-replay safe) ----------------
__global__ void zero_counters_kernel() {
    int i = blockIdx.x * blockDim.x + threadIdx.x;
    if (i < Bn * NC) d_cand_cnt[i] = 0;
    if (i < Bn) d_img_cnt[i] = 0;
}

// ---------------- kernel 1: warp-per-row softmax + threshold + decode ----------------
__global__ void softmax_gather_kernel(const float* __restrict__ logits,
                                      const float* __restrict__ boxreg,
                                      const float* __restrict__ props) {
    const int wid = threadIdx.x >> 5;
    const int lane = threadIdx.x & 31;
    const int row = blockIdx.x * ROWS_PER_CTA + wid;   // grid = B*N/8 = 4000
    const int b = row / Nn;
    const int n = row % Nn;

    const float* L = logits + (size_t)row * Cn;

    float l[4];
    #pragma unroll
    for (int q = 0; q < 4; q++) {
        const int j = lane + 32 * q;
        l[q] = (j < Cn) ? L[j] : -INFINITY;
    }

    float mx = fmaxf(fmaxf(l[0], l[1]), fmaxf(l[2], l[3]));
    #pragma unroll
    for (int o = 16; o > 0; o >>= 1) mx = fmaxf(mx, __shfl_xor_sync(0xffffffffu, mx, o));

    float eh[4];
    float s = 0.0f;
    #pragma unroll
    for (int q = 0; q < 4; q++) {
        const int j = lane + 32 * q;
        eh[q] = (j < Cn) ? __expf(l[q] - mx) : 0.0f;
        s += eh[q];
    }
    #pragma unroll
    for (int o = 16; o > 0; o >>= 1) s += __shfl_xor_sync(0xffffffffu, s, o);
    float inv_s = 1.0f / s;

    float ph[4];
    bool amb = false;
    #pragma unroll
    for (int q = 0; q < 4; q++) {
        const int j = lane + 32 * q;
        ph[q] = eh[q] * inv_s;
        if (j >= 1 && j < Cn && fabsf(ph[q] - SCORE_TH) < AMB_BAND) amb = true;
    }
    bool precise_row = false;
    if (__ballot_sync(0xffffffffu, amb)) {
        float sp = 0.0f;
        #pragma unroll
        for (int q = 0; q < 4; q++) {
            const int j = lane + 32 * q;
            eh[q] = (j < Cn) ? expf(l[q] - mx) : 0.0f;
            sp += eh[q];
        }
        #pragma unroll
        for (int o = 16; o > 0; o >>= 1) sp += __shfl_xor_sync(0xffffffffu, sp, o);
        inv_s = 1.0f / sp;
        #pragma unroll
        for (int q = 0; q < 4; q++) ph[q] = eh[q] * inv_s;
        precise_row = true;
    }

    const float4 pr = *(const float4*)(props + (size_t)row * 4);
    const float w  = pr.z - pr.x + 1.0f;
    const float h  = pr.w - pr.y + 1.0f;
    const float cx = pr.x + 0.5f * w;
    const float cy = pr.y + 0.5f * h;

    #pragma unroll
    for (int q = 0; q < 4; q++) {
        const int j = lane + 32 * q;
        if (j >= 1 && j < Cn && ph[q] > SCORE_TH) {
            const float p_store = precise_row ? ph[q] : expf(l[q] - mx) * inv_s;

            const float4 r = *(const float4*)(boxreg + ((size_t)row * Cn + j) * 4);
            const float dx = r.x / 10.0f;
            const float dy = r.y / 10.0f;
            const float dw = fminf(r.z / 5.0f, BBOX_CLIP);
            const float dh = fminf(r.w / 5.0f, BBOX_CLIP);
            const float pcx = dx * w + cx;
            const float pcy = dy * h + cy;
            const float pw = expf(dw) * w;
            const float ph2 = expf(dh) * h;
            float4 box;
            box.x = fminf(fmaxf(pcx - 0.5f * pw, 0.0f), IMG_W - 1.0f);
            box.y = fminf(fmaxf(pcy - 0.5f * ph2, 0.0f), IMG_H - 1.0f);
            box.z = fminf(fmaxf(pcx + 0.5f * pw - 1.0f, 0.0f), IMG_W - 1.0f);
            box.w = fminf(fmaxf(pcy + 0.5f * ph2 - 1.0f, 0.0f), IMG_H - 1.0f);

            const int c = j - 1;
            const int slot = atomicAdd(&d_cand_cnt[b * NC + c], 1);
            d_cand_score[b][c][slot] = p_store;
            d_cand_n[b][c][slot] = n;
            d_cand_box[b][c][slot] = box;
        }
    }
}

// ---------------- kernel 2: merged NMS (warp / mask / fallback paths) ----------------
struct SmemMid {
    unsigned long long skey[KMASK];
    float4 sbox[KMASK];       // slot order
    float4 sbox2[KMASK];      // rank order
    float  sarea[KMASK];      // rank order
    short  perm[KMASK];       // rank -> slot
    short  rnk[KMASK];        // slot -> rank
    unsigned mask[KMASK * NWM];
    unsigned suppw[NWM];
};
struct SmemBig {
    float  ss[MAXCAND];
    int    sn[MAXCAND];
    short  sslot[MAXCAND];
    float4 sbox[MAXCAND];
    unsigned char supp[MAXCAND];
};
union SmemU {
    SmemMid mid;
    SmemBig big;
};

__global__ void nms_kernel() {
    __shared__ SmemU u;

    const int bc = blockIdx.x;           // 0 .. B*NC-1
    const int K = d_cand_cnt[bc];
    if (K == 0) return;
    const int b = bc / NC;
    const int c = bc % NC;
    const int tid = threadIdx.x;         // NMS_THREADS = 256

    // ================= path A: K <= 32, warp 0 only, register/shuffle =================
    if (K <= 32) {
        if (tid >= 32) return;
        const int lane = tid;

        if (K == 1) {
            if (lane == 0) {
                const int pos = atomicAdd(&d_img_cnt[b], 1);
                d_det_score[b][pos] = d_cand_score[b][c][0];
                d_det_box[b][pos] = d_cand_box[b][c][0];
                d_det_label[b][pos] = c + 1;
            }
            return;
        }

        const bool act = lane < K;
        const float sc = act ? d_cand_score[b][c][lane] : -INFINITY;
        const int   nn = act ? d_cand_n[b][c][lane] : 0x7fffffff;
        float4 bx = make_float4(0.0f, 0.0f, 0.0f, 0.0f);
        if (act) bx = d_cand_box[b][c][lane];

        int rank = 0;
        #pragma unroll 8
        for (int l = 0; l < 32; l++) {
            const float osc = __shfl_sync(0xffffffffu, sc, l);
            const int   onn = __shfl_sync(0xffffffffu, nn, l);
            if (osc > sc || (osc == sc && onn < nn)) rank++;
        }

        const float area = (bx.z - bx.x + 1.0f) * (bx.w - bx.y + 1.0f);

        unsigned myrow = 0;
        #pragma unroll 8
        for (int l = 0; l < 32; l++) {
            const int   orank = __shfl_sync(0xffffffffu, rank, l);
            const float ox1 = __shfl_sync(0xffffffffu, bx.x, l);
            const float oy1 = __shfl_sync(0xffffffffu, bx.y, l);
            const float ox2 = __shfl_sync(0xffffffffu, bx.z, l);
            const float oy2 = __shfl_sync(0xffffffffu, bx.w, l);
            const float oarea = __shfl_sync(0xffffffffu, area, l);
            const bool oact = (orank < K);
            if (act && oact && orank > rank) {
                const float iw = fmaxf(fminf(ox2, bx.z) - fmaxf(ox1, bx.x) + 1.0f, 0.0f);
                const float ih = fmaxf(fminf(oy2, bx.w) - fmaxf(oy1, bx.y) + 1.0f, 0.0f);
                const float inter = iw * ih;
                const float iou = inter / (area + oarea - inter);
                if (iou > NMS_TH) myrow |= 1u << orank;
            }
        }
        unsigned rows[32];
        #pragma unroll 8
        for (int l = 0; l < 32; l++) {
            const int   orank = __shfl_sync(0xffffffffu, rank, l);
            const unsigned orow = __shfl_sync(0xffffffffu, myrow, l);
            if (orank < 32) rows[orank] = orow;
        }
        unsigned suppm = 0;
        for (int t = 0; t < K; t++) {
            if (!((suppm >> t) & 1u)) suppm |= rows[t];
        }

        const bool keep = act && !((suppm >> rank) & 1u);
        const unsigned km = __ballot_sync(0xffffffffu, keep);
        const int cnt = __popc(km);
        if (cnt == 0) return;
        const int leader = __ffs(km) - 1;
        int base = 0;
        if (lane == leader) base = atomicAdd(&d_img_cnt[b], cnt);
        base = __shfl_sync(0xffffffffu, base, leader);
        if (keep) {
            const int pos = base + __popc(km & ((1u << lane) - 1u));
            d_det_score[b][pos] = sc;
            d_det_box[b][pos] = bx;
            d_det_label[b][pos] = c + 1;
        }
        return;
    }

    // ================= path B: 32 < K <= KMASK, rank + mask, chunked scan =================
    if (K <= KMASK) {
        for (int i = tid; i < K; i += NMS_THREADS) {
            const unsigned sb = __float_as_uint(d_cand_score[b][c][i]);
            u.mid.skey[i] = ((unsigned long long)sb << 32) |
                            (unsigned)(0x7fffffff - d_cand_n[b][c][i]);
            u.mid.sbox[i] = d_cand_box[b][c][i];
        }
        __syncthreads();

        for (int i = tid; i < K; i += NMS_THREADS) {
            const unsigned long long me = u.mid.skey[i];
            int r = 0;
            for (int j = 0; j < K; j++) r += (u.mid.skey[j] > me);
            u.mid.rnk[i] = (short)r;
            u.mid.perm[r] = (short)i;
        }
        __syncthreads();

        for (int r = tid; r < K; r += NMS_THREADS) {
            const float4 A = u.mid.sbox[u.mid.perm[r]];
            u.mid.sbox2[r] = A;
            u.mid.sarea[r] = (A.z - A.x + 1.0f) * (A.w - A.y + 1.0f);
        }
        __syncthreads();

        const int nw = (K + 31) >> 5;
        const int totalWork = K * nw;
        for (int t = tid; t < totalWork; t += NMS_THREADS) {
            const int r = t / nw;
            const int w = t - r * nw;
            const int jbase = w << 5;
            const int jend = min(jbase + 32, K);
            unsigned m = 0;
            if (jend > r + 1) {
                const float4 A = u.mid.sbox2[r];
                const float areaA = u.mid.sarea[r];
                for (int j = max(jbase, r + 1); j < jend; j++) {
                    const float4 Bx = u.mid.sbox2[j];
                    const float iw = fmaxf(fminf(A.z, Bx.z) - fmaxf(A.x, Bx.x) + 1.0f, 0.0f);
                    const float ih = fmaxf(fminf(A.w, Bx.w) - fmaxf(A.y, Bx.y) + 1.0f, 0.0f);
                    const float inter = iw * ih;
                    const float iou = inter / (areaA + u.mid.sarea[j] - inter);
                    if (iou > NMS_TH) m |= 1u << (j & 31);
                }
            }
            u.mid.mask[r * NWM + w] = m;
        }
        __syncthreads();

        // chunked greedy scan by warp 0: one shuffle per 32 ranks
        if (tid < 32) {
            unsigned sw = 0;
            for (int cch = 0; cch < nw; cch++) {
                unsigned cur = __shfl_sync(0xffffffffu, sw, cch);
                const int iend = min(32, K - (cch << 5));
                unsigned keptbits = 0;
                #pragma unroll
                for (int t = 0; t < 32; t++) {
                    const unsigned rowword = u.mid.mask[((cch << 5) + t) * NWM + cch];
                    if (t < iend && !((cur >> t) & 1u)) {
                        cur |= rowword;
                        keptbits |= 1u << t;
                    }
                }
                if (tid == cch) sw = cur;
                else if (tid > cch && tid < nw) {
                    unsigned kb = keptbits;
                    while (kb) {
                        const int t = __ffs(kb) - 1;
                        kb &= kb - 1;
                        sw |= u.mid.mask[((cch << 5) + t) * NWM + tid];
                    }
                }
            }
            if (tid < nw) u.mid.suppw[tid] = sw;
        }
        __syncthreads();

        for (int i = tid; i < K; i += NMS_THREADS) {
            const int r = u.mid.rnk[i];
            if (!((u.mid.suppw[r >> 5] >> (r & 31)) & 1u)) {
                const int pos = atomicAdd(&d_img_cnt[b], 1);
                d_det_score[b][pos] = __uint_as_float((unsigned)(u.mid.skey[i] >> 32));
                d_det_box[b][pos] = u.mid.sbox[i];
                d_det_label[b][pos] = c + 1;
            }
        }
        return;
    }

    // ================= path C: K > KMASK fallback (sort + greedy) =================
    int P = 1;
    while (P < K) P <<= 1;

    for (int i = tid; i < P; i += NMS_THREADS) {
        if (i < K) {
            u.big.ss[i] = d_cand_score[b][c][i];
            u.big.sn[i] = d_cand_n[b][c][i];
            u.big.sbox[i] = d_cand_box[b][c][i];
        } else {
            u.big.ss[i] = -INFINITY;
            u.big.sn[i] = 0x7fffffff;
        }
        u.big.sslot[i] = (short)i;
        u.big.supp[i] = (i >= K);
    }
    __syncthreads();

    for (int k = 2; k <= P; k <<= 1) {
        for (int j = k >> 1; j > 0; j >>= 1) {
            for (int i = tid; i < P; i += NMS_THREADS) {
                const int ixj = i ^ j;
                if (ixj > i) {
                    const float a = u.big.ss[i], bb = u.big.ss[ixj];
                    const int   na = u.big.sn[i], nb = u.big.sn[ixj];
                    const bool i_after = (a < bb) || (a == bb && na > nb);
                    const bool dirAsc = ((i & k) == 0);
                    if (i_after == dirAsc) {
                        u.big.ss[i] = bb;  u.big.ss[ixj] = a;
                        u.big.sn[i] = nb;  u.big.sn[ixj] = na;
                        const short t = u.big.sslot[i];
                        u.big.sslot[i] = u.big.sslot[ixj];
                        u.big.sslot[ixj] = t;
                    }
                }
            }
            __syncthreads();
        }
    }

    for (int i = 0; i < K; i++) {
        __syncthreads();
        if (u.big.supp[i]) continue;
        const float4 A = u.big.sbox[u.big.sslot[i]];
        const float areaA = (A.z - A.x + 1.0f) * (A.w - A.y + 1.0f);
        for (int j = i + 1 + tid; j < K; j += NMS_THREADS) {
            if (u.big.supp[j]) continue;
            const float4 Bx = u.big.sbox[u.big.sslot[j]];
            const float iw = fmaxf(fminf(A.z, Bx.z) - fmaxf(A.x, Bx.x) + 1.0f, 0.0f);
            const float ih = fmaxf(fminf(A.w, Bx.w) - fmaxf(A.y, Bx.y) + 1.0f, 0.0f);
            const float inter = iw * ih;
            const float areaB = (Bx.z - Bx.x + 1.0f) * (Bx.w - Bx.y + 1.0f);
            const float iou = inter / (areaA + areaB - inter);
            if (iou > NMS_TH) u.big.supp[j] = 1;
        }
    }
    __syncthreads();
    for (int i = tid; i < K; i += NMS_THREADS) {
        if (!u.big.supp[i]) {
            const int pos = atomicAdd(&d_img_cnt[b], 1);
            d_det_score[b][pos] = u.big.ss[i];
            d_det_box[b][pos] = u.big.sbox[u.big.sslot[i]];
            d_det_label[b][pos] = c + 1;
        }
    }
}

// ---------------- kernel 3: per-image top-100 via radix select + rank scatter ----------------
__global__ void topk_kernel(float* __restrict__ out) {
    const int b = blockIdx.x;
    const int tid = threadIdx.x;     // TOPK_THREADS = 512
    const int M = d_img_cnt[b];

    float* detOut = out + (size_t)b * DETS * 5;
    float* labOut = out + (size_t)Bn * DETS * 5 + (size_t)b * DETS;
    float* valOut = out + (size_t)Bn * DETS * 5 + (size_t)Bn * DETS + (size_t)b * DETS;

    __shared__ int hist[256];
    __shared__ int wsum[8];          // per-warp scan totals
    __shared__ unsigned s_prefix;
    __shared__ int s_rank;
    __shared__ int s_cnt;
    __shared__ unsigned long long keys[GCAP];
    __shared__ unsigned long long ord[DETS];   // rank -> key

    // -------- phase 1: radix select bit-pattern T of the DETS-th largest score --------
    unsigned T = 0u;                 // if M < DETS: keep everything
    if (M >= DETS) {
        if (tid == 0) { s_prefix = 0u; s_rank = DETS; }
        __syncthreads();
        for (int shift = 24; shift >= 0; shift -= 8) {
            if (tid < 256) hist[tid] = 0;
            __syncthreads();
            const unsigned pfx = s_prefix;
            const int rank = s_rank;
            const unsigned hmask = (shift == 24) ? 0u : (0xffffffffu << (shift + 8));
            for (int i = tid; i < M; i += TOPK_THREADS) {
                const unsigned bits = __float_as_uint(d_det_score[b][i]);
                if ((bits & hmask) == (pfx & hmask))
                    atomicAdd(&hist[(bits >> shift) & 255], 1);
            }
            __syncthreads();

            // parallel digit selection: thread tid<256 owns bin d = 255 - tid.
            if (tid < 256) {
                const int d = 255 - tid;
                const int v = hist[d];
                const int lane = tid & 31;
                const int wrp = tid >> 5;
                int incl = v;
                #pragma unroll
                for (int o = 1; o < 32; o <<= 1) {
                    const int other = __shfl_up_sync(0xffffffffu, incl, o);
                    if (lane >= o) incl += other;
                }
                if (lane == 31) wsum[wrp] = incl;
                __syncwarp();
            }
            __syncthreads();
            if (tid < 256) {
                const int d = 255 - tid;
                const int v = hist[d];
                const int lane = tid & 31;
                const int wrp = tid >> 5;
                int incl = v;
                #pragma unroll
                for (int o = 1; o < 32; o <<= 1) {
                    const int other = __shfl_up_sync(0xffffffffu, incl, o);
                    if (lane >= o) incl += other;
                }
                int off = 0;
                #pragma unroll
                for (int wq = 0; wq < 8; wq++) if (wq < wrp) off += wsum[wq];
                incl += off;
                const int excl = incl - v;
                if (excl < rank && rank <= incl) {   // exactly one thread
                    s_prefix = pfx | ((unsigned)d << shift);
                    s_rank = rank - excl;
                }
            }
            __syncthreads();
        }
        T = s_prefix;
    }

    // -------- phase 2: gather all elements with bits >= T --------
    if (tid == 0) s_cnt = 0;
    if (tid < DETS) ord[tid] = 0ull;
    __syncthreads();
    for (int i = tid; i < M; i += TOPK_THREADS) {
        const unsigned bits = __float_as_uint(d_det_score[b][i]);
        if (bits >= T) {
            const int p = atomicAdd(&s_cnt, 1);
            if (p < GCAP)
                keys[p] = ((unsigned long long)bits << 32) |
                          (unsigned)(0x7fffffff - i);
        }
    }
    __syncthreads();
    const int cnt = (s_cnt < GCAP) ? s_cnt : GCAP;

    // -------- phase 3: rank by counting (keys unique) + scatter into ord --------
    for (int p = tid; p < cnt; p += TOPK_THREADS) {
        const unsigned long long me = keys[p];
        int r = 0;
        for (int j = 0; j < cnt; j++) r += (keys[j] > me);
        if (r < DETS) ord[r] = me;
    }
    __syncthreads();

    // -------- phase 4: parallel output write --------
    if (tid < DETS) {
        const unsigned long long key = ord[tid];
        if (key != 0ull) {
            const int idx = 0x7fffffff - (int)(unsigned)(key & 0xffffffffull);
            const float score = __uint_as_float((unsigned)(key >> 32));
            const float4 bx = d_det_box[b][idx];
            detOut[tid * 5 + 0] = bx.x;
            detOut[tid * 5 + 1] = bx.y;
            detOut[tid * 5 + 2] = bx.z;
            detOut[tid * 5 + 3] = bx.w;
            detOut[tid * 5 + 4] = score;
            labOut[tid] = (float)d_det_label[b][idx];
            valOut[tid] = 1.0f;
        } else {
            detOut[tid * 5 + 0] = 0.0f;
            detOut[tid * 5 + 1] = 0.0f;
            detOut[tid * 5 + 2] = 0.0f;
            detOut[tid * 5 + 3] = 0.0f;
            detOut[tid * 5 + 4] = 0.0f;
            labOut[tid] = 0.0f;
            valOut[tid] = 0.0f;
        }
    }
}

// ---------------- launch ----------------
extern "C" void kernel_launch(void* const* d_in, const int* in_sizes, int n_in,
                              void* d_out, int out_size) {
    const float* logits = nullptr;
    const float* boxreg = nullptr;
    const float* props  = nullptr;
    for (int i = 0; i < n_in; i++) {
        if (in_sizes[i] == Bn * Nn * Cn)          logits = (const float*)d_in[i];
        else if (in_sizes[i] == Bn * Nn * 4 * Cn) boxreg = (const float*)d_in[i];
        else if (in_sizes[i] == Bn * Nn * 4)      props = (const float*)d_in[i];
    }
    float* out = (float*)d_out;

    zero_counters_kernel<<<(Bn * NC + 255) / 256, 256>>>();
    softmax_gather_kernel<<<(Bn * Nn) / ROWS_PER_CTA, 32 * ROWS_PER_CTA>>>(logits, boxreg, props);
    nms_kernel<<<Bn * NC, NMS_THREADS>>>();
    topk_kernel<<<Bn, TOPK_THREADS>>>(out);
}